// round 1
// baseline (speedup 1.0000x reference)
#include <cuda_runtime.h>
#include <math.h>

namespace {
constexpr int B  = 16,  LAT = 256, D  = 256, DI = 512, DS = 16, DTR = 16;
constexpr int L  = 1024, KC = 4,  OUTD = 64, NL = 4;
constexpr int NR = B * L;  // 16384 rows of (b, t)
}

// ---------------- scratch (static device globals; no allocation) ----------
__device__ float g_h   [NR * D];
__device__ float g_xn  [NR * D];
__device__ float g_xz  [NR * 2 * DI];
__device__ float g_xs  [NR * DI];
__device__ float g_dbc [NR * 48];
__device__ float g_dt  [NR * DI];
__device__ float g_y   [NR * DI];
__device__ float g_base[B * D];

// ---------------- helpers --------------------------------------------------
__device__ __forceinline__ float geluf(float x) {
  return 0.5f * x * (1.f + erff(x * 0.70710678118654752f));
}
__device__ __forceinline__ float siluf(float x) {
  return x / (1.f + __expf(-x));
}

__device__ __forceinline__ float blk_sum_256(float v, float* red) {
  __syncthreads();
  int lane = threadIdx.x & 31, w = threadIdx.x >> 5;
#pragma unroll
  for (int o = 16; o; o >>= 1) v += __shfl_xor_sync(0xffffffffu, v, o);
  if (lane == 0) red[w] = v;
  __syncthreads();
  if (threadIdx.x < 32) {
    float t = (threadIdx.x < 8) ? red[threadIdx.x] : 0.f;
#pragma unroll
    for (int o = 4; o; o >>= 1) t += __shfl_xor_sync(0xffffffffu, t, o);
    if (threadIdx.x == 0) red[0] = t;
  }
  __syncthreads();
  return red[0];
}

// ---------------- base = gelu(LN(z) @ lw.T + bias) -------------------------
__global__ void k_base(const float* __restrict__ z, const float* __restrict__ lg,
                       const float* __restrict__ lb, const float* __restrict__ lw,
                       const float* __restrict__ lbias) {
  __shared__ float xn[LAT];
  __shared__ float red[32];
  int b = blockIdx.x, tid = threadIdx.x;
  float v  = z[b * LAT + tid];
  float mu = blk_sum_256(v, red) * (1.f / LAT);
  float dv = v - mu;
  float var = blk_sum_256(dv * dv, red) * (1.f / LAT);
  float inv = rsqrtf(var + 1e-5f);
  xn[tid] = dv * inv * lg[tid] + lb[tid];
  __syncthreads();
  float acc = lbias[tid];
  const float* wr = lw + tid * LAT;
#pragma unroll 8
  for (int k = 0; k < LAT; ++k) acc = fmaf(xn[k], wr[k], acc);
  g_base[b * D + tid] = geluf(acc);
}

// ---------------- h = base[b,None,:] + time_emb ----------------------------
__global__ void k_fillh(const float* __restrict__ temb) {
  int idx = blockIdx.x * blockDim.x + threadIdx.x;  // NR*D
  int d = idx & (D - 1);
  int t = (idx >> 8) & (L - 1);
  int b = idx >> 18;
  g_h[idx] = g_base[b * D + d] + temb[t * D + d];
}

// ---------------- LayerNorm over D=256, warp per row -----------------------
__global__ void k_ln(const float* __restrict__ x, const float* __restrict__ g,
                     const float* __restrict__ be, float* __restrict__ o) {
  int row  = blockIdx.x * 8 + (threadIdx.x >> 5);
  int lane = threadIdx.x & 31;
  const float* xr = x + (size_t)row * D;
  float v[8];
  float s = 0.f;
#pragma unroll
  for (int j = 0; j < 8; ++j) { v[j] = xr[lane + 32 * j]; s += v[j]; }
#pragma unroll
  for (int o2 = 16; o2; o2 >>= 1) s += __shfl_xor_sync(0xffffffffu, s, o2);
  float mu = s * (1.f / D);
  float s2 = 0.f;
#pragma unroll
  for (int j = 0; j < 8; ++j) { float dv = v[j] - mu; s2 += dv * dv; }
#pragma unroll
  for (int o2 = 16; o2; o2 >>= 1) s2 += __shfl_xor_sync(0xffffffffu, s2, o2);
  float inv = rsqrtf(s2 * (1.f / D) + 1e-5f);
  float* orow = o + (size_t)row * D;
#pragma unroll
  for (int j = 0; j < 8; ++j) {
    int c = lane + 32 * j;
    orow[c] = (v[j] - mu) * inv * g[c] + be[c];
  }
}

// ---------------- SGEMM: C(MxN) = A(MxK) @ B(NxK)^T [+bias][+=C] -----------
template <int BM, int BN, int BK, int TM, int TN, bool ACCUM>
__global__ void __launch_bounds__((BM / TM) * (BN / TN))
sgemm_nt(const float* __restrict__ A, const float* __restrict__ Bm,
         const float* __restrict__ bias, float* __restrict__ C,
         int M, int N, int K) {
  constexpr int NT = (BM / TM) * (BN / TN);
  __shared__ float As[BK][BM];
  __shared__ float Bs[BK][BN];
  int tid = threadIdx.x;
  int bn = blockIdx.x, bm = blockIdx.y;
  const float* Ab = A  + (size_t)bm * BM * K;
  const float* Bb = Bm + (size_t)bn * BN * K;
  int tx = tid % (BN / TN), ty = tid / (BN / TN);
  float acc[TM][TN] = {};
  for (int k0 = 0; k0 < K; k0 += BK) {
    for (int i = tid * 4; i < BM * BK; i += NT * 4) {
      int r = i / BK, c = i % BK;
      float4 v = *reinterpret_cast<const float4*>(Ab + (size_t)r * K + k0 + c);
      As[c + 0][r] = v.x; As[c + 1][r] = v.y; As[c + 2][r] = v.z; As[c + 3][r] = v.w;
    }
    for (int i = tid * 4; i < BN * BK; i += NT * 4) {
      int r = i / BK, c = i % BK;
      float4 v = *reinterpret_cast<const float4*>(Bb + (size_t)r * K + k0 + c);
      Bs[c + 0][r] = v.x; Bs[c + 1][r] = v.y; Bs[c + 2][r] = v.z; Bs[c + 3][r] = v.w;
    }
    __syncthreads();
#pragma unroll
    for (int k = 0; k < BK; ++k) {
      float ra[TM], rb[TN];
#pragma unroll
      for (int i = 0; i < TM; ++i) ra[i] = As[k][ty * TM + i];
#pragma unroll
      for (int j = 0; j < TN; ++j) rb[j] = Bs[k][tx * TN + j];
#pragma unroll
      for (int i = 0; i < TM; ++i)
#pragma unroll
        for (int j = 0; j < TN; ++j) acc[i][j] = fmaf(ra[i], rb[j], acc[i][j]);
    }
    __syncthreads();
  }
#pragma unroll
  for (int i = 0; i < TM; ++i) {
    int m = bm * BM + ty * TM + i;
    float* Cr = C + (size_t)m * N + bn * BN + tx * TN;
#pragma unroll
    for (int j = 0; j < TN; ++j) {
      float v = acc[i][j];
      if (bias) v += bias[bn * BN + tx * TN + j];
      if (ACCUM) v += Cr[j];
      Cr[j] = v;
    }
  }
}

// ---------------- depthwise causal conv (K=4) + silu -----------------------
__global__ void k_conv(const float* __restrict__ w, const float* __restrict__ cb) {
  int idx = blockIdx.x * blockDim.x + threadIdx.x;  // NR*DI
  int d = idx & (DI - 1);
  int t = (idx >> 9) & (L - 1);
  int b = idx >> 19;
  const float* base = g_xz + (size_t)(b * L) * (2 * DI);
  float acc = cb[d];
#pragma unroll
  for (int k = 0; k < KC; ++k) {
    int tt = t + k - (KC - 1);
    if (tt >= 0) acc = fmaf(base[(size_t)tt * (2 * DI) + d], w[d * KC + k], acc);
  }
  g_xs[idx] = siluf(acc);
}

// ---------------- dbc = xs @ xp_w^T  (N=48, warp per row) ------------------
__global__ void k_dbc(const float* __restrict__ xpw) {
  int warp = (blockIdx.x * blockDim.x + threadIdx.x) >> 5;
  int lane = threadIdx.x & 31;
  const float* xr = g_xs + (size_t)warp * DI;
  float v[16];
#pragma unroll
  for (int j = 0; j < 16; ++j) v[j] = xr[lane + 32 * j];
  float* orow = g_dbc + (size_t)warp * 48;
  for (int n = 0; n < 48; ++n) {
    const float* w = xpw + (size_t)n * DI;
    float acc = 0.f;
#pragma unroll
    for (int j = 0; j < 16; ++j) acc = fmaf(v[j], w[lane + 32 * j], acc);
#pragma unroll
    for (int o = 16; o; o >>= 1) acc += __shfl_xor_sync(0xffffffffu, acc, o);
    if (lane == 0) orow[n] = acc;
  }
}

// ---------------- dt = softplus(dbc[:, :16] @ dt_w^T + dt_b) ---------------
__global__ void k_dt(const float* __restrict__ dtw, const float* __restrict__ dtb) {
  int idx = blockIdx.x * blockDim.x + threadIdx.x;  // NR*DI
  int d   = idx & (DI - 1);
  int row = idx >> 9;
  const float* r = g_dbc + (size_t)row * 48;
  const float* w = dtw + (size_t)d * DTR;
  float acc = dtb[d];
#pragma unroll
  for (int k = 0; k < DTR; ++k) acc = fmaf(r[k], w[k], acc);
  g_dt[idx] = (acc > 20.f) ? acc : log1pf(__expf(acc));
}

// ---------------- selective scan + gating epilogue --------------------------
// grid = B*8 blocks (b, 64-wide d chunk), 1024 threads = 64 d x 16 s.
__global__ void __launch_bounds__(1024) k_scan(const float* __restrict__ A_log,
                                               const float* __restrict__ Dp) {
  int b  = blockIdx.x >> 3;
  int dc = blockIdx.x & 7;
  int s  = threadIdx.x & 15;
  int d  = dc * 64 + (threadIdx.x >> 4);
  float a  = -expf(A_log[d * DS + s]);
  float dp = Dp[d];
  float h = 0.f;
  int rowbase = b * L;
  const float* pdt = g_dt  + (size_t)rowbase * DI + d;
  const float* pxs = g_xs  + (size_t)rowbase * DI + d;
  const float* pB  = g_dbc + (size_t)rowbase * 48 + 16 + s;
  const float* pC  = g_dbc + (size_t)rowbase * 48 + 32 + s;
  const float* pzg = g_xz  + (size_t)rowbase * (2 * DI) + DI + d;
  float*       py  = g_y   + (size_t)rowbase * DI + d;

  float dtv = pdt[0], xv = pxs[0], Bv = pB[0], Cv = pC[0];
  for (int t = 0; t < L; ++t) {
    int adv = (t < L - 1);
    // prefetch next step while computing this one
    float ndt = pdt[adv * DI];
    float nx  = pxs[adv * DI];
    float nB  = pB [adv * 48];
    float nC  = pC [adv * 48];

    float e = __expf(dtv * a);
    h = fmaf(e, h, dtv * xv * Bv);
    float val = h * Cv;
#pragma unroll
    for (int o = 8; o; o >>= 1) val += __shfl_xor_sync(0xffffffffu, val, o, 16);
    if (s == 0) {
      float zg = *pzg;
      py[0] = (val + xv * dp) * siluf(zg);
    }
    dtv = ndt; xv = nx; Bv = nB; Cv = nC;
    pdt += DI; pxs += DI; pB += 48; pC += 48; pzg += 2 * DI; py += DI;
  }
}

// ---------------- launch ----------------------------------------------------
extern "C" void kernel_launch(void* const* d_in, const int* in_sizes, int n_in,
                              void* d_out, int out_size) {
  const float* z      = (const float*)d_in[0];
  const float* lg     = (const float*)d_in[1];
  const float* lb     = (const float*)d_in[2];
  const float* lw     = (const float*)d_in[3];
  const float* lbias  = (const float*)d_in[4];
  const float* temb   = (const float*)d_in[5];
  const float* ln_g   = (const float*)d_in[6];
  const float* ln_b   = (const float*)d_in[7];
  const float* in_w   = (const float*)d_in[8];
  const float* in_b   = (const float*)d_in[9];
  const float* conv_w = (const float*)d_in[10];
  const float* conv_b = (const float*)d_in[11];
  const float* xp_w   = (const float*)d_in[12];
  const float* dt_w   = (const float*)d_in[13];
  const float* dt_b   = (const float*)d_in[14];
  const float* A_log  = (const float*)d_in[15];
  const float* Dp     = (const float*)d_in[16];
  const float* out_w  = (const float*)d_in[17];
  const float* out_b  = (const float*)d_in[18];
  const float* on_g   = (const float*)d_in[19];
  const float* on_b   = (const float*)d_in[20];
  const float* op_w   = (const float*)d_in[21];
  const float* op_b   = (const float*)d_in[22];
  float* out = (float*)d_out;

  float *p_h, *p_xn, *p_xz, *p_xs, *p_y;
  cudaGetSymbolAddress((void**)&p_h,  g_h);
  cudaGetSymbolAddress((void**)&p_xn, g_xn);
  cudaGetSymbolAddress((void**)&p_xz, g_xz);
  cudaGetSymbolAddress((void**)&p_xs, g_xs);
  cudaGetSymbolAddress((void**)&p_y,  g_y);

  k_base<<<B, LAT>>>(z, lg, lb, lw, lbias);
  k_fillh<<<NR * D / 256, 256>>>(temb);

  for (int i = 0; i < NL; ++i) {
    k_ln<<<NR / 8, 256>>>(p_h, ln_g + i * D, ln_b + i * D, p_xn);
    sgemm_nt<128, 128, 8, 8, 8, false>
        <<<dim3(2 * DI / 128, NR / 128), 256>>>(
            p_xn, in_w + (size_t)i * 2 * DI * D, in_b + i * 2 * DI, p_xz,
            NR, 2 * DI, D);
    k_conv<<<NR * DI / 256, 256>>>(conv_w + i * DI * KC, conv_b + i * DI);
    k_dbc<<<NR / 8, 256>>>(xp_w + (size_t)i * 48 * DI);
    k_dt<<<NR * DI / 256, 256>>>(dt_w + i * DI * DTR, dt_b + i * DI);
    k_scan<<<B * 8, 1024>>>(A_log + i * DI * DS, Dp + i * DI);
    sgemm_nt<128, 128, 8, 8, 8, true>
        <<<dim3(D / 128, NR / 128), 256>>>(
            p_y, out_w + (size_t)i * D * DI, out_b + i * D, p_h,
            NR, D, DI);
  }

  k_ln<<<NR / 8, 256>>>(p_h, on_g, on_b, p_xn);
  sgemm_nt<128, 64, 8, 8, 4, false>
      <<<dim3(1, NR / 128), 256>>>(p_xn, op_w, op_b, out, NR, OUTD, D);
}

// round 3
// speedup vs baseline: 1.2676x; 1.2676x over previous
#include <cuda_runtime.h>
#include <cuda_bf16.h>
#include <math.h>
#include <stdint.h>

namespace {
constexpr int B  = 16,  LAT = 256, D  = 256, DI = 512, DS = 16, DTR = 16;
constexpr int L  = 1024, KC = 4,  OUTD = 64, NL = 4;
constexpr int NR = B * L;  // 16384 rows of (b, t)
}

// ---------------- scratch (static device globals; no allocation) ----------
__device__ float g_h   [NR * D];
__device__ float g_xn  [NR * D];
__device__ float g_xz  [NR * 2 * DI];
__device__ float g_xs  [NR * DI];
__device__ float g_dbc [NR * 48];
__device__ float g_dt  [NR * DI];
__device__ float g_base[B * D];
// split-bf16 activations / weights for tensor-core GEMMs
__device__ __nv_bfloat16 g_xnh[NR * D],  g_xnl[NR * D];
__device__ __nv_bfloat16 g_yh [NR * DI], g_yl [NR * DI];
__device__ __nv_bfloat16 g_wih[NL * 2 * DI * D], g_wil[NL * 2 * DI * D];
__device__ __nv_bfloat16 g_woh[NL * D * DI],     g_wol[NL * D * DI];

// ---------------- PTX helpers ----------------------------------------------
__device__ __forceinline__ uint32_t smem_u32(const void* p) {
  uint32_t a;
  asm("{ .reg .u64 t; cvta.to.shared.u64 t, %1; cvt.u32.u64 %0, t; }"
      : "=r"(a) : "l"(p));
  return a;
}
__device__ __forceinline__ void cp16(uint32_t dst, const void* src) {
  asm volatile("cp.async.cg.shared.global [%0], [%1], 16;" ::"r"(dst),
               "l"(src));
}
__device__ __forceinline__ void cp_commit() {
  asm volatile("cp.async.commit_group;" ::: "memory");
}
template <int N>
__device__ __forceinline__ void cp_wait() {
  asm volatile("cp.async.wait_group %0;" ::"n"(N) : "memory");
}
__device__ __forceinline__ void ldsm4(uint32_t (&r)[4], uint32_t addr) {
  asm volatile(
      "ldmatrix.sync.aligned.m8n8.x4.shared.b16 {%0,%1,%2,%3}, [%4];"
      : "=r"(r[0]), "=r"(r[1]), "=r"(r[2]), "=r"(r[3])
      : "r"(addr));
}
__device__ __forceinline__ void mma16816(float (&d)[4], const uint32_t (&a)[4],
                                         uint32_t b0, uint32_t b1) {
  asm volatile(
      "mma.sync.aligned.m16n8k16.row.col.f32.bf16.bf16.f32 "
      "{%0,%1,%2,%3}, {%4,%5,%6,%7}, {%8,%9}, {%0,%1,%2,%3};"
      : "+f"(d[0]), "+f"(d[1]), "+f"(d[2]), "+f"(d[3])
      : "r"(a[0]), "r"(a[1]), "r"(a[2]), "r"(a[3]), "r"(b0), "r"(b1));
}

// ---------------- math helpers ---------------------------------------------
__device__ __forceinline__ float geluf(float x) {
  return 0.5f * x * (1.f + erff(x * 0.70710678118654752f));
}
__device__ __forceinline__ float siluf(float x) {
  return x / (1.f + __expf(-x));
}
__device__ __forceinline__ float blk_sum_256(float v, float* red) {
  __syncthreads();
  int lane = threadIdx.x & 31, w = threadIdx.x >> 5;
#pragma unroll
  for (int o = 16; o; o >>= 1) v += __shfl_xor_sync(0xffffffffu, v, o);
  if (lane == 0) red[w] = v;
  __syncthreads();
  if (threadIdx.x < 32) {
    float t = (threadIdx.x < 8) ? red[threadIdx.x] : 0.f;
#pragma unroll
    for (int o = 4; o; o >>= 1) t += __shfl_xor_sync(0xffffffffu, t, o);
    if (threadIdx.x == 0) red[0] = t;
  }
  __syncthreads();
  return red[0];
}

// ---------------- HMMA GEMM: C(MxN) = A@B^T + bias [+C], split-bf16 --------
// A = Ah+Al (M x K row-major), B = Bh+Bl (N x K row-major).
// C = AhBh + AhBl + AlBh (fp32 accumulate in registers).
// Block tile 128x128, BK=32, 8 warps (4m x 2n), warp tile 32x64.
// smem: per stage 4 arrays of 128 rows x 40 bf16 (pad 32->40: conflict-free
// ldmatrix, 80B row stride). 2 stages, cp.async pipeline.
constexpr int LDSE   = 40;                 // smem row stride (elements)
constexpr int ARR_B  = 128 * LDSE * 2;     // 10240 bytes per array
constexpr int STG_B  = 4 * ARR_B;          // 40960 bytes per stage
constexpr int SMEM_H = 2 * STG_B;          // 81920

template <bool ACCUM>
__global__ void __launch_bounds__(256)
hmma_gemm(const __nv_bfloat16* __restrict__ Ah,
          const __nv_bfloat16* __restrict__ Al,
          const __nv_bfloat16* __restrict__ Bh,
          const __nv_bfloat16* __restrict__ Bl,
          const float* __restrict__ bias, float* __restrict__ C,
          int N, int K) {
  extern __shared__ char smem[];
  const uint32_t sb = smem_u32(smem);
  const int tid = threadIdx.x, lane = tid & 31, wid = tid >> 5;
  const int wm = wid >> 1, wn = wid & 1;
  const int m0 = blockIdx.y * 128, n0 = blockIdx.x * 128;

  float acc[2][8][4] = {};

  const int nchunk = K >> 5;

  // ---- async-copy one 32-wide K chunk into stage s
  auto issue = [&](int s, int k0) {
    uint32_t st = sb + s * STG_B;
#pragma unroll
    for (int i = 0; i < 2; ++i) {
      int seg = tid + i * 256;           // 0..511
      int r = seg >> 2, c4 = seg & 3;    // row 0..127, 16B chunk 0..3
      uint32_t so = r * (LDSE * 2) + c4 * 16;
      size_t goA = (size_t)(m0 + r) * K + k0 + c4 * 8;
      size_t goB = (size_t)(n0 + r) * K + k0 + c4 * 8;
      cp16(st + 0 * ARR_B + so, Ah + goA);
      cp16(st + 1 * ARR_B + so, Al + goA);
      cp16(st + 2 * ARR_B + so, Bh + goB);
      cp16(st + 3 * ARR_B + so, Bl + goB);
    }
    cp_commit();
  };

  auto compute = [&](int s) {
    uint32_t st = sb + s * STG_B;
#pragma unroll
    for (int ks = 0; ks < 32; ks += 16) {
      uint32_t aH[2][4], aL[2][4], bH[4][4], bL[4][4];
#pragma unroll
      for (int mi = 0; mi < 2; ++mi) {
        uint32_t ro = wm * 32 + mi * 16 + (lane & 15);
        uint32_t co = ks + ((lane >> 4) & 1) * 8;
        uint32_t ad = st + (ro * LDSE + co) * 2;
        ldsm4(aH[mi], ad);
        ldsm4(aL[mi], ad + ARR_B);
      }
#pragma unroll
      for (int p = 0; p < 4; ++p) {
        uint32_t nr = wn * 64 + p * 16 + (lane & 7) + ((lane >> 4) & 1) * 8;
        uint32_t kc = ks + ((lane >> 3) & 1) * 8;
        uint32_t ad = st + 2 * ARR_B + (nr * LDSE + kc) * 2;
        ldsm4(bH[p], ad);
        ldsm4(bL[p], ad + ARR_B);
      }
      // pass 1: Ah * Bh
#pragma unroll
      for (int mi = 0; mi < 2; ++mi)
#pragma unroll
        for (int ni = 0; ni < 8; ++ni)
          mma16816(acc[mi][ni], aH[mi], bH[ni >> 1][(ni & 1) * 2],
                   bH[ni >> 1][(ni & 1) * 2 + 1]);
      // pass 2: Ah * Bl
#pragma unroll
      for (int mi = 0; mi < 2; ++mi)
#pragma unroll
        for (int ni = 0; ni < 8; ++ni)
          mma16816(acc[mi][ni], aH[mi], bL[ni >> 1][(ni & 1) * 2],
                   bL[ni >> 1][(ni & 1) * 2 + 1]);
      // pass 3: Al * Bh
#pragma unroll
      for (int mi = 0; mi < 2; ++mi)
#pragma unroll
        for (int ni = 0; ni < 8; ++ni)
          mma16816(acc[mi][ni], aL[mi], bH[ni >> 1][(ni & 1) * 2],
                   bH[ni >> 1][(ni & 1) * 2 + 1]);
    }
  };

  issue(0, 0);
  for (int c = 0; c < nchunk; ++c) {
    if (c + 1 < nchunk) {
      issue((c + 1) & 1, (c + 1) * 32);
      cp_wait<1>();
    } else {
      cp_wait<0>();
    }
    __syncthreads();
    compute(c & 1);
    __syncthreads();
  }

  // ---- epilogue
  const int mb = m0 + wm * 32 + (lane >> 2);
  const int nb = n0 + wn * 64 + (lane & 3) * 2;
#pragma unroll
  for (int mi = 0; mi < 2; ++mi) {
#pragma unroll
    for (int ni = 0; ni < 8; ++ni) {
      int c = nb + ni * 8;
      float b0 = bias[c], b1 = bias[c + 1];
      float* p0 = C + (size_t)(mb + mi * 16) * N + c;
      float* p1 = C + (size_t)(mb + mi * 16 + 8) * N + c;
      float2 v0 = make_float2(acc[mi][ni][0] + b0, acc[mi][ni][1] + b1);
      float2 v1 = make_float2(acc[mi][ni][2] + b0, acc[mi][ni][3] + b1);
      if (ACCUM) {
        float2 o0 = *reinterpret_cast<float2*>(p0);
        float2 o1 = *reinterpret_cast<float2*>(p1);
        v0.x += o0.x; v0.y += o0.y; v1.x += o1.x; v1.y += o1.y;
      }
      *reinterpret_cast<float2*>(p0) = v0;
      *reinterpret_cast<float2*>(p1) = v1;
    }
  }
}

// ---------------- fp32 -> split bf16 ---------------------------------------
__global__ void k_cvt(const float* __restrict__ s, __nv_bfloat16* __restrict__ h,
                      __nv_bfloat16* __restrict__ l, int n) {
  int i = blockIdx.x * blockDim.x + threadIdx.x;
  if (i < n) {
    float v = s[i];
    __nv_bfloat16 hi = __float2bfloat16_rn(v);
    h[i] = hi;
    l[i] = __float2bfloat16_rn(v - __bfloat162float(hi));
  }
}

// ---------------- base = gelu(LN(z) @ lw.T + bias) -------------------------
__global__ void k_base(const float* __restrict__ z, const float* __restrict__ lg,
                       const float* __restrict__ lb, const float* __restrict__ lw,
                       const float* __restrict__ lbias) {
  __shared__ float xn[LAT];
  __shared__ float red[32];
  int b = blockIdx.x, tid = threadIdx.x;
  float v  = z[b * LAT + tid];
  float mu = blk_sum_256(v, red) * (1.f / LAT);
  float dv = v - mu;
  float var = blk_sum_256(dv * dv, red) * (1.f / LAT);
  float inv = rsqrtf(var + 1e-5f);
  xn[tid] = dv * inv * lg[tid] + lb[tid];
  __syncthreads();
  float acc = lbias[tid];
  const float* wr = lw + tid * LAT;
#pragma unroll 8
  for (int k = 0; k < LAT; ++k) acc = fmaf(xn[k], wr[k], acc);
  g_base[b * D + tid] = geluf(acc);
}

__global__ void k_fillh(const float* __restrict__ temb) {
  int idx = blockIdx.x * blockDim.x + threadIdx.x;
  int d = idx & (D - 1);
  int t = (idx >> 8) & (L - 1);
  int b = idx >> 18;
  g_h[idx] = g_base[b * D + d] + temb[t * D + d];
}

// ---------------- LayerNorm (warp per row) ---------------------------------
template <bool BF>
__global__ void k_ln_t(const float* __restrict__ x, const float* __restrict__ g,
                       const float* __restrict__ be, float* __restrict__ o,
                       __nv_bfloat16* __restrict__ oh,
                       __nv_bfloat16* __restrict__ ol) {
  int row  = blockIdx.x * 8 + (threadIdx.x >> 5);
  int lane = threadIdx.x & 31;
  const float* xr = x + (size_t)row * D;
  float v[8];
  float s = 0.f;
#pragma unroll
  for (int j = 0; j < 8; ++j) { v[j] = xr[lane + 32 * j]; s += v[j]; }
#pragma unroll
  for (int o2 = 16; o2; o2 >>= 1) s += __shfl_xor_sync(0xffffffffu, s, o2);
  float mu = s * (1.f / D);
  float s2 = 0.f;
#pragma unroll
  for (int j = 0; j < 8; ++j) { float dv = v[j] - mu; s2 += dv * dv; }
#pragma unroll
  for (int o2 = 16; o2; o2 >>= 1) s2 += __shfl_xor_sync(0xffffffffu, s2, o2);
  float inv = rsqrtf(s2 * (1.f / D) + 1e-5f);
#pragma unroll
  for (int j = 0; j < 8; ++j) {
    int c = lane + 32 * j;
    float r = (v[j] - mu) * inv * g[c] + be[c];
    if (BF) {
      __nv_bfloat16 hi = __float2bfloat16_rn(r);
      oh[(size_t)row * D + c] = hi;
      ol[(size_t)row * D + c] = __float2bfloat16_rn(r - __bfloat162float(hi));
    } else {
      o[(size_t)row * D + c] = r;
    }
  }
}

// ---------------- SGEMM (fp32, small final GEMM only) ----------------------
template <int BM, int BN, int BK, int TM, int TN>
__global__ void __launch_bounds__((BM / TM) * (BN / TN))
sgemm_nt(const float* __restrict__ A, const float* __restrict__ Bm,
         const float* __restrict__ bias, float* __restrict__ C,
         int M, int N, int K) {
  constexpr int NT = (BM / TM) * (BN / TN);
  __shared__ float As[BK][BM];
  __shared__ float Bs[BK][BN];
  int tid = threadIdx.x;
  int bn = blockIdx.x, bm = blockIdx.y;
  const float* Ab = A  + (size_t)bm * BM * K;
  const float* Bb = Bm + (size_t)bn * BN * K;
  int tx = tid % (BN / TN), ty = tid / (BN / TN);
  float acc[TM][TN] = {};
  for (int k0 = 0; k0 < K; k0 += BK) {
    for (int i = tid * 4; i < BM * BK; i += NT * 4) {
      int r = i / BK, c = i % BK;
      float4 v = *reinterpret_cast<const float4*>(Ab + (size_t)r * K + k0 + c);
      As[c + 0][r] = v.x; As[c + 1][r] = v.y; As[c + 2][r] = v.z; As[c + 3][r] = v.w;
    }
    for (int i = tid * 4; i < BN * BK; i += NT * 4) {
      int r = i / BK, c = i % BK;
      float4 v = *reinterpret_cast<const float4*>(Bb + (size_t)r * K + k0 + c);
      Bs[c + 0][r] = v.x; Bs[c + 1][r] = v.y; Bs[c + 2][r] = v.z; Bs[c + 3][r] = v.w;
    }
    __syncthreads();
#pragma unroll
    for (int k = 0; k < BK; ++k) {
      float ra[TM], rb[TN];
#pragma unroll
      for (int i = 0; i < TM; ++i) ra[i] = As[k][ty * TM + i];
#pragma unroll
      for (int j = 0; j < TN; ++j) rb[j] = Bs[k][tx * TN + j];
#pragma unroll
      for (int i = 0; i < TM; ++i)
#pragma unroll
        for (int j = 0; j < TN; ++j) acc[i][j] = fmaf(ra[i], rb[j], acc[i][j]);
    }
    __syncthreads();
  }
#pragma unroll
  for (int i = 0; i < TM; ++i) {
    int m = bm * BM + ty * TM + i;
    float* Cr = C + (size_t)m * N + bn * BN + tx * TN;
#pragma unroll
    for (int j = 0; j < TN; ++j) Cr[j] = acc[i][j] + bias[bn * BN + tx * TN + j];
  }
}

// ---------------- depthwise causal conv (K=4) + silu -----------------------
__global__ void k_conv(const float* __restrict__ w, const float* __restrict__ cb) {
  int idx = blockIdx.x * blockDim.x + threadIdx.x;
  int d = idx & (DI - 1);
  int t = (idx >> 9) & (L - 1);
  int b = idx >> 19;
  const float* base = g_xz + (size_t)(b * L) * (2 * DI);
  float acc = cb[d];
#pragma unroll
  for (int k = 0; k < KC; ++k) {
    int tt = t + k - (KC - 1);
    if (tt >= 0) acc = fmaf(base[(size_t)tt * (2 * DI) + d], w[d * KC + k], acc);
  }
  g_xs[idx] = siluf(acc);
}

// ---------------- dbc = xs @ xp_w^T  (N=48, warp per row) ------------------
__global__ void k_dbc(const float* __restrict__ xpw) {
  int warp = (blockIdx.x * blockDim.x + threadIdx.x) >> 5;
  int lane = threadIdx.x & 31;
  const float* xr = g_xs + (size_t)warp * DI;
  float v[16];
#pragma unroll
  for (int j = 0; j < 16; ++j) v[j] = xr[lane + 32 * j];
  float* orow = g_dbc + (size_t)warp * 48;
  for (int n = 0; n < 48; ++n) {
    const float* w = xpw + (size_t)n * DI;
    float acc = 0.f;
#pragma unroll
    for (int j = 0; j < 16; ++j) acc = fmaf(v[j], w[lane + 32 * j], acc);
#pragma unroll
    for (int o = 16; o; o >>= 1) acc += __shfl_xor_sync(0xffffffffu, acc, o);
    if (lane == 0) orow[n] = acc;
  }
}

// ---------------- dt = softplus(dbc[:, :16] @ dt_w^T + dt_b) ---------------
__global__ void k_dt(const float* __restrict__ dtw, const float* __restrict__ dtb) {
  int idx = blockIdx.x * blockDim.x + threadIdx.x;
  int d   = idx & (DI - 1);
  int row = idx >> 9;
  const float* r = g_dbc + (size_t)row * 48;
  const float* w = dtw + (size_t)d * DTR;
  float acc = dtb[d];
#pragma unroll
  for (int k = 0; k < DTR; ++k) acc = fmaf(r[k], w[k], acc);
  g_dt[idx] = (acc > 20.f) ? acc : log1pf(__expf(acc));
}

// ---------------- selective scan + gating epilogue --------------------------
__global__ void __launch_bounds__(1024) k_scan(const float* __restrict__ A_log,
                                               const float* __restrict__ Dp) {
  int b  = blockIdx.x >> 3;
  int dc = blockIdx.x & 7;
  int s  = threadIdx.x & 15;
  int d  = dc * 64 + (threadIdx.x >> 4);
  float a  = -expf(A_log[d * DS + s]);
  float dp = Dp[d];
  float h = 0.f;
  int rowbase = b * L;
  const float* pdt = g_dt  + (size_t)rowbase * DI + d;
  const float* pxs = g_xs  + (size_t)rowbase * DI + d;
  const float* pB  = g_dbc + (size_t)rowbase * 48 + 16 + s;
  const float* pC  = g_dbc + (size_t)rowbase * 48 + 32 + s;
  const float* pzg = g_xz  + (size_t)rowbase * (2 * DI) + DI + d;
  __nv_bfloat16* pyh = g_yh + (size_t)rowbase * DI + d;
  __nv_bfloat16* pyl = g_yl + (size_t)rowbase * DI + d;

  float dtv = pdt[0], xv = pxs[0], Bv = pB[0], Cv = pC[0];
  for (int t = 0; t < L; ++t) {
    int adv = (t < L - 1);
    float ndt = pdt[adv * DI];
    float nx  = pxs[adv * DI];
    float nB  = pB [adv * 48];
    float nC  = pC [adv * 48];

    float e = __expf(dtv * a);
    h = fmaf(e, h, dtv * xv * Bv);
    float val = h * Cv;
#pragma unroll
    for (int o = 8; o; o >>= 1) val += __shfl_xor_sync(0xffffffffu, val, o, 16);
    if (s == 0) {
      float zg = *pzg;
      float vy = (val + xv * dp) * siluf(zg);
      __nv_bfloat16 hb = __float2bfloat16_rn(vy);
      pyh[0] = hb;
      pyl[0] = __float2bfloat16_rn(vy - __bfloat162float(hb));
    }
    dtv = ndt; xv = nx; Bv = nB; Cv = nC;
    pdt += DI; pxs += DI; pB += 48; pC += 48; pzg += 2 * DI;
    pyh += DI; pyl += DI;
  }
}

// ---------------- launch ----------------------------------------------------
extern "C" void kernel_launch(void* const* d_in, const int* in_sizes, int n_in,
                              void* d_out, int out_size) {
  const float* z      = (const float*)d_in[0];
  const float* lg     = (const float*)d_in[1];
  const float* lb     = (const float*)d_in[2];
  const float* lw     = (const float*)d_in[3];
  const float* lbias  = (const float*)d_in[4];
  const float* temb   = (const float*)d_in[5];
  const float* ln_g   = (const float*)d_in[6];
  const float* ln_b   = (const float*)d_in[7];
  const float* in_w   = (const float*)d_in[8];
  const float* in_b   = (const float*)d_in[9];
  const float* conv_w = (const float*)d_in[10];
  const float* conv_b = (const float*)d_in[11];
  const float* xp_w   = (const float*)d_in[12];
  const float* dt_w   = (const float*)d_in[13];
  const float* dt_b   = (const float*)d_in[14];
  const float* A_log  = (const float*)d_in[15];
  const float* Dp     = (const float*)d_in[16];
  const float* out_w  = (const float*)d_in[17];
  const float* out_b  = (const float*)d_in[18];
  const float* on_g   = (const float*)d_in[19];
  const float* on_b   = (const float*)d_in[20];
  const float* op_w   = (const float*)d_in[21];
  const float* op_b   = (const float*)d_in[22];
  float* out = (float*)d_out;

  float *p_h, *p_xn, *p_xz;
  __nv_bfloat16 *p_xnh, *p_xnl, *p_yh, *p_yl, *p_wih, *p_wil, *p_woh, *p_wol;
  cudaGetSymbolAddress((void**)&p_h,   g_h);
  cudaGetSymbolAddress((void**)&p_xn,  g_xn);
  cudaGetSymbolAddress((void**)&p_xz,  g_xz);
  cudaGetSymbolAddress((void**)&p_xnh, g_xnh);
  cudaGetSymbolAddress((void**)&p_xnl, g_xnl);
  cudaGetSymbolAddress((void**)&p_yh,  g_yh);
  cudaGetSymbolAddress((void**)&p_yl,  g_yl);
  cudaGetSymbolAddress((void**)&p_wih, g_wih);
  cudaGetSymbolAddress((void**)&p_wil, g_wil);
  cudaGetSymbolAddress((void**)&p_woh, g_woh);
  cudaGetSymbolAddress((void**)&p_wol, g_wol);

  cudaFuncSetAttribute(hmma_gemm<false>,
                       cudaFuncAttributeMaxDynamicSharedMemorySize, SMEM_H);
  cudaFuncSetAttribute(hmma_gemm<true>,
                       cudaFuncAttributeMaxDynamicSharedMemorySize, SMEM_H);

  // one-time (per launch) weight splits
  const int NIW = NL * 2 * DI * D, NOW = NL * D * DI;
  k_cvt<<<(NIW + 255) / 256, 256>>>(in_w, p_wih, p_wil, NIW);
  k_cvt<<<(NOW + 255) / 256, 256>>>(out_w, p_woh, p_wol, NOW);

  k_base<<<B, LAT>>>(z, lg, lb, lw, lbias);
  k_fillh<<<NR * D / 256, 256>>>(temb);

  for (int i = 0; i < NL; ++i) {
    k_ln_t<true><<<NR / 8, 256>>>(p_h, ln_g + i * D, ln_b + i * D, nullptr,
                                  p_xnh, p_xnl);
    // xz = LN(h) @ in_w^T + in_b   (M=16384, N=1024, K=256)
    hmma_gemm<false><<<dim3(8, NR / 128), 256, SMEM_H>>>(
        p_xnh, p_xnl, p_wih + (size_t)i * 2 * DI * D,
        p_wil + (size_t)i * 2 * DI * D, in_b + i * 2 * DI, p_xz, 2 * DI, D);
    k_conv<<<NR * DI / 256, 256>>>(conv_w + i * DI * KC, conv_b + i * DI);
    k_dbc<<<NR / 8, 256>>>(xp_w + (size_t)i * 48 * DI);
    k_dt<<<NR * DI / 256, 256>>>(dt_w + i * DI * DTR, dt_b + i * DI);
    k_scan<<<B * 8, 1024>>>(A_log + i * DI * DS, Dp + i * DI);
    // h += y @ out_w^T + out_b    (M=16384, N=256, K=512)
    hmma_gemm<true><<<dim3(2, NR / 128), 256, SMEM_H>>>(
        p_yh, p_yl, p_woh + (size_t)i * D * DI, p_wol + (size_t)i * D * DI,
        out_b + i * D, p_h, D, DI);
  }

  k_ln_t<false><<<NR / 8, 256>>>(p_h, on_g, on_b, p_xn, nullptr, nullptr);
  sgemm_nt<128, 64, 8, 8, 4>
      <<<dim3(1, NR / 128), 256>>>(p_xn, op_w, op_b, out, NR, OUTD, D);
}

// round 4
// speedup vs baseline: 1.7100x; 1.3490x over previous
#include <cuda_runtime.h>
#include <cuda_bf16.h>
#include <math.h>
#include <stdint.h>

namespace {
constexpr int B  = 16,  LAT = 256, D  = 256, DI = 512, DS = 16, DTR = 16;
constexpr int L  = 1024, KC = 4,  OUTD = 64, NL = 4;
constexpr int NR = B * L;  // 16384 rows of (b, t)
}

// ---------------- scratch (static device globals; no allocation) ----------
__device__ float g_h   [NR * D];
__device__ float g_xn  [NR * D];
__device__ float g_xz  [NR * 2 * DI];
__device__ float g_xs  [NR * DI];
__device__ float g_dbc [NR * 48];
__device__ float g_dt  [NR * DI];
__device__ float g_base[B * D];
__device__ __nv_bfloat16 g_xnh[NR * D],  g_xnl[NR * D];
__device__ __nv_bfloat16 g_yh [NR * DI], g_yl [NR * DI];
__device__ __nv_bfloat16 g_wih[NL * 2 * DI * D], g_wil[NL * 2 * DI * D];
__device__ __nv_bfloat16 g_woh[NL * D * DI],     g_wol[NL * D * DI];

// ---------------- PTX helpers ----------------------------------------------
__device__ __forceinline__ uint32_t smem_u32(const void* p) {
  uint32_t a;
  asm("{ .reg .u64 t; cvta.to.shared.u64 t, %1; cvt.u32.u64 %0, t; }"
      : "=r"(a) : "l"(p));
  return a;
}
__device__ __forceinline__ void cp16(uint32_t dst, const void* src) {
  asm volatile("cp.async.cg.shared.global [%0], [%1], 16;" ::"r"(dst),
               "l"(src));
}
__device__ __forceinline__ void cp_commit() {
  asm volatile("cp.async.commit_group;" ::: "memory");
}
template <int N>
__device__ __forceinline__ void cp_wait() {
  asm volatile("cp.async.wait_group %0;" ::"n"(N) : "memory");
}
__device__ __forceinline__ void ldsm4(uint32_t (&r)[4], uint32_t addr) {
  asm volatile(
      "ldmatrix.sync.aligned.m8n8.x4.shared.b16 {%0,%1,%2,%3}, [%4];"
      : "=r"(r[0]), "=r"(r[1]), "=r"(r[2]), "=r"(r[3])
      : "r"(addr));
}
__device__ __forceinline__ void mma16816(float (&d)[4], const uint32_t (&a)[4],
                                         uint32_t b0, uint32_t b1) {
  asm volatile(
      "mma.sync.aligned.m16n8k16.row.col.f32.bf16.bf16.f32 "
      "{%0,%1,%2,%3}, {%4,%5,%6,%7}, {%8,%9}, {%0,%1,%2,%3};"
      : "+f"(d[0]), "+f"(d[1]), "+f"(d[2]), "+f"(d[3])
      : "r"(a[0]), "r"(a[1]), "r"(a[2]), "r"(a[3]), "r"(b0), "r"(b1));
}

// ---------------- math helpers ---------------------------------------------
__device__ __forceinline__ float geluf(float x) {
  return 0.5f * x * (1.f + erff(x * 0.70710678118654752f));
}
__device__ __forceinline__ float siluf(float x) {
  return x / (1.f + __expf(-x));
}
__device__ __forceinline__ float blk_sum_256(float v, float* red) {
  __syncthreads();
  int lane = threadIdx.x & 31, w = threadIdx.x >> 5;
#pragma unroll
  for (int o = 16; o; o >>= 1) v += __shfl_xor_sync(0xffffffffu, v, o);
  if (lane == 0) red[w] = v;
  __syncthreads();
  if (threadIdx.x < 32) {
    float t = (threadIdx.x < 8) ? red[threadIdx.x] : 0.f;
#pragma unroll
    for (int o = 4; o; o >>= 1) t += __shfl_xor_sync(0xffffffffu, t, o);
    if (threadIdx.x == 0) red[0] = t;
  }
  __syncthreads();
  return red[0];
}

// ---------------- HMMA GEMM: C = A@B^T + bias [+C], split-bf16 -------------
constexpr int LDSE   = 40;
constexpr int ARR_B  = 128 * LDSE * 2;
constexpr int STG_B  = 4 * ARR_B;
constexpr int SMEM_H = 2 * STG_B;  // 81920

template <bool ACCUM>
__global__ void __launch_bounds__(256, 2)
hmma_gemm(const __nv_bfloat16* __restrict__ Ah,
          const __nv_bfloat16* __restrict__ Al,
          const __nv_bfloat16* __restrict__ Bh,
          const __nv_bfloat16* __restrict__ Bl,
          const float* __restrict__ bias, float* __restrict__ C,
          int N, int K) {
  extern __shared__ char smem[];
  const uint32_t sb = smem_u32(smem);
  const int tid = threadIdx.x, lane = tid & 31, wid = tid >> 5;
  const int wm = wid >> 1, wn = wid & 1;
  const int m0 = blockIdx.y * 128, n0 = blockIdx.x * 128;

  float acc[2][8][4] = {};
  const int nchunk = K >> 5;

  auto issue = [&](int s, int k0) {
    uint32_t st = sb + s * STG_B;
#pragma unroll
    for (int i = 0; i < 2; ++i) {
      int seg = tid + i * 256;
      int r = seg >> 2, c4 = seg & 3;
      uint32_t so = r * (LDSE * 2) + c4 * 16;
      size_t goA = (size_t)(m0 + r) * K + k0 + c4 * 8;
      size_t goB = (size_t)(n0 + r) * K + k0 + c4 * 8;
      cp16(st + 0 * ARR_B + so, Ah + goA);
      cp16(st + 1 * ARR_B + so, Al + goA);
      cp16(st + 2 * ARR_B + so, Bh + goB);
      cp16(st + 3 * ARR_B + so, Bl + goB);
    }
    cp_commit();
  };

  auto compute = [&](int s) {
    uint32_t st = sb + s * STG_B;
#pragma unroll
    for (int ks = 0; ks < 32; ks += 16) {
      uint32_t aH[2][4], aL[2][4];
#pragma unroll
      for (int mi = 0; mi < 2; ++mi) {
        uint32_t ro = wm * 32 + mi * 16 + (lane & 15);
        uint32_t co = ks + ((lane >> 4) & 1) * 8;
        uint32_t ad = st + (ro * LDSE + co) * 2;
        ldsm4(aH[mi], ad);
        ldsm4(aL[mi], ad + ARR_B);
      }
#pragma unroll
      for (int p = 0; p < 4; ++p) {
        uint32_t bh[4], bl[4];
        uint32_t nr = wn * 64 + p * 16 + (lane & 7) + ((lane >> 4) & 1) * 8;
        uint32_t kc = ks + ((lane >> 3) & 1) * 8;
        uint32_t ad = st + 2 * ARR_B + (nr * LDSE + kc) * 2;
        ldsm4(bh, ad);
        ldsm4(bl, ad + ARR_B);
#pragma unroll
        for (int mi = 0; mi < 2; ++mi) {
#pragma unroll
          for (int q = 0; q < 2; ++q) {
            mma16816(acc[mi][p * 2 + q], aH[mi], bh[q * 2], bh[q * 2 + 1]);
            mma16816(acc[mi][p * 2 + q], aH[mi], bl[q * 2], bl[q * 2 + 1]);
            mma16816(acc[mi][p * 2 + q], aL[mi], bh[q * 2], bh[q * 2 + 1]);
          }
        }
      }
    }
  };

  issue(0, 0);
  for (int c = 0; c < nchunk; ++c) {
    if (c + 1 < nchunk) {
      issue((c + 1) & 1, (c + 1) * 32);
      cp_wait<1>();
    } else {
      cp_wait<0>();
    }
    __syncthreads();
    compute(c & 1);
    __syncthreads();
  }

  const int mb = m0 + wm * 32 + (lane >> 2);
  const int nb = n0 + wn * 64 + (lane & 3) * 2;
#pragma unroll
  for (int mi = 0; mi < 2; ++mi) {
#pragma unroll
    for (int ni = 0; ni < 8; ++ni) {
      int c = nb + ni * 8;
      float b0 = bias[c], b1 = bias[c + 1];
      float* p0 = C + (size_t)(mb + mi * 16) * N + c;
      float* p1 = C + (size_t)(mb + mi * 16 + 8) * N + c;
      float2 v0 = make_float2(acc[mi][ni][0] + b0, acc[mi][ni][1] + b1);
      float2 v1 = make_float2(acc[mi][ni][2] + b0, acc[mi][ni][3] + b1);
      if (ACCUM) {
        float2 o0 = *reinterpret_cast<float2*>(p0);
        float2 o1 = *reinterpret_cast<float2*>(p1);
        v0.x += o0.x; v0.y += o0.y; v1.x += o1.x; v1.y += o1.y;
      }
      *reinterpret_cast<float2*>(p0) = v0;
      *reinterpret_cast<float2*>(p1) = v1;
    }
  }
}

// ---------------- fp32 -> split bf16 ---------------------------------------
__global__ void k_cvt(const float* __restrict__ s, __nv_bfloat16* __restrict__ h,
                      __nv_bfloat16* __restrict__ l, int n) {
  int i = blockIdx.x * blockDim.x + threadIdx.x;
  if (i < n) {
    float v = s[i];
    __nv_bfloat16 hi = __float2bfloat16_rn(v);
    h[i] = hi;
    l[i] = __float2bfloat16_rn(v - __bfloat162float(hi));
  }
}

// ---------------- base = gelu(LN(z) @ lw.T + bias) -------------------------
__global__ void k_base(const float* __restrict__ z, const float* __restrict__ lg,
                       const float* __restrict__ lb, const float* __restrict__ lw,
                       const float* __restrict__ lbias) {
  __shared__ float xn[LAT];
  __shared__ float red[32];
  int b = blockIdx.x, tid = threadIdx.x;
  float v  = z[b * LAT + tid];
  float mu = blk_sum_256(v, red) * (1.f / LAT);
  float dv = v - mu;
  float var = blk_sum_256(dv * dv, red) * (1.f / LAT);
  float inv = rsqrtf(var + 1e-5f);
  xn[tid] = dv * inv * lg[tid] + lb[tid];
  __syncthreads();
  float acc = lbias[tid];
  const float* wr = lw + tid * LAT;
#pragma unroll 8
  for (int k = 0; k < LAT; ++k) acc = fmaf(xn[k], wr[k], acc);
  g_base[b * D + tid] = geluf(acc);
}

__global__ void k_fillh(const float* __restrict__ temb) {
  int idx = blockIdx.x * blockDim.x + threadIdx.x;
  int d = idx & (D - 1);
  int t = (idx >> 8) & (L - 1);
  int b = idx >> 18;
  g_h[idx] = g_base[b * D + d] + temb[t * D + d];
}

// ---------------- LayerNorm (warp per row) ---------------------------------
template <bool BF>
__global__ void k_ln_t(const float* __restrict__ x, const float* __restrict__ g,
                       const float* __restrict__ be, float* __restrict__ o,
                       __nv_bfloat16* __restrict__ oh,
                       __nv_bfloat16* __restrict__ ol) {
  int row  = blockIdx.x * 8 + (threadIdx.x >> 5);
  int lane = threadIdx.x & 31;
  const float* xr = x + (size_t)row * D;
  float v[8];
  float s = 0.f;
#pragma unroll
  for (int j = 0; j < 8; ++j) { v[j] = xr[lane + 32 * j]; s += v[j]; }
#pragma unroll
  for (int o2 = 16; o2; o2 >>= 1) s += __shfl_xor_sync(0xffffffffu, s, o2);
  float mu = s * (1.f / D);
  float s2 = 0.f;
#pragma unroll
  for (int j = 0; j < 8; ++j) { float dv = v[j] - mu; s2 += dv * dv; }
#pragma unroll
  for (int o2 = 16; o2; o2 >>= 1) s2 += __shfl_xor_sync(0xffffffffu, s2, o2);
  float inv = rsqrtf(s2 * (1.f / D) + 1e-5f);
#pragma unroll
  for (int j = 0; j < 8; ++j) {
    int c = lane + 32 * j;
    float r = (v[j] - mu) * inv * g[c] + be[c];
    if (BF) {
      __nv_bfloat16 hi = __float2bfloat16_rn(r);
      oh[(size_t)row * D + c] = hi;
      ol[(size_t)row * D + c] = __float2bfloat16_rn(r - __bfloat162float(hi));
    } else {
      o[(size_t)row * D + c] = r;
    }
  }
}

// ---------------- SGEMM (fp32, small final GEMM only) ----------------------
template <int BM, int BN, int BK, int TM, int TN>
__global__ void __launch_bounds__((BM / TM) * (BN / TN))
sgemm_nt(const float* __restrict__ A, const float* __restrict__ Bm,
         const float* __restrict__ bias, float* __restrict__ C,
         int M, int N, int K) {
  constexpr int NT = (BM / TM) * (BN / TN);
  __shared__ float As[BK][BM];
  __shared__ float Bs[BK][BN];
  int tid = threadIdx.x;
  int bn = blockIdx.x, bm = blockIdx.y;
  const float* Ab = A  + (size_t)bm * BM * K;
  const float* Bb = Bm + (size_t)bn * BN * K;
  int tx = tid % (BN / TN), ty = tid / (BN / TN);
  float acc[TM][TN] = {};
  for (int k0 = 0; k0 < K; k0 += BK) {
    for (int i = tid * 4; i < BM * BK; i += NT * 4) {
      int r = i / BK, c = i % BK;
      float4 v = *reinterpret_cast<const float4*>(Ab + (size_t)r * K + k0 + c);
      As[c + 0][r] = v.x; As[c + 1][r] = v.y; As[c + 2][r] = v.z; As[c + 3][r] = v.w;
    }
    for (int i = tid * 4; i < BN * BK; i += NT * 4) {
      int r = i / BK, c = i % BK;
      float4 v = *reinterpret_cast<const float4*>(Bb + (size_t)r * K + k0 + c);
      Bs[c + 0][r] = v.x; Bs[c + 1][r] = v.y; Bs[c + 2][r] = v.z; Bs[c + 3][r] = v.w;
    }
    __syncthreads();
#pragma unroll
    for (int k = 0; k < BK; ++k) {
      float ra[TM], rb[TN];
#pragma unroll
      for (int i = 0; i < TM; ++i) ra[i] = As[k][ty * TM + i];
#pragma unroll
      for (int j = 0; j < TN; ++j) rb[j] = Bs[k][tx * TN + j];
#pragma unroll
      for (int i = 0; i < TM; ++i)
#pragma unroll
        for (int j = 0; j < TN; ++j) acc[i][j] = fmaf(ra[i], rb[j], acc[i][j]);
    }
    __syncthreads();
  }
#pragma unroll
  for (int i = 0; i < TM; ++i) {
    int m = bm * BM + ty * TM + i;
    float* Cr = C + (size_t)m * N + bn * BN + tx * TN;
#pragma unroll
    for (int j = 0; j < TN; ++j) Cr[j] = acc[i][j] + bias[bn * BN + tx * TN + j];
  }
}

// ---------------- depthwise causal conv (K=4) + silu, float4 ---------------
__global__ void k_conv(const float* __restrict__ w, const float* __restrict__ cb) {
  int idx = blockIdx.x * blockDim.x + threadIdx.x;  // NR*DI/4
  int d4 = idx & (DI / 4 - 1);
  int t  = (idx >> 7) & (L - 1);
  int b  = idx >> 17;
  int d  = d4 * 4;
  const float* base = g_xz + (size_t)(b * L) * (2 * DI) + d;
  float4 wv[KC];
#pragma unroll
  for (int k = 0; k < KC; ++k) {
    wv[k].x = w[(d + 0) * KC + k];
    wv[k].y = w[(d + 1) * KC + k];
    wv[k].z = w[(d + 2) * KC + k];
    wv[k].w = w[(d + 3) * KC + k];
  }
  float4 acc = *reinterpret_cast<const float4*>(cb + d);
#pragma unroll
  for (int k = 0; k < KC; ++k) {
    int tt = t + k - (KC - 1);
    if (tt >= 0) {
      float4 x = *reinterpret_cast<const float4*>(base + (size_t)tt * (2 * DI));
      acc.x = fmaf(x.x, wv[k].x, acc.x);
      acc.y = fmaf(x.y, wv[k].y, acc.y);
      acc.z = fmaf(x.z, wv[k].z, acc.z);
      acc.w = fmaf(x.w, wv[k].w, acc.w);
    }
  }
  float4 o;
  o.x = siluf(acc.x); o.y = siluf(acc.y); o.z = siluf(acc.z); o.w = siluf(acc.w);
  *reinterpret_cast<float4*>(g_xs + (size_t)idx * 4) = o;
}

// ---------------- dbc = xs @ xp_w^T (N=48): 2 rows/warp, float4 ------------
__global__ void __launch_bounds__(256) k_dbc(const float* __restrict__ xpw) {
  int gw   = blockIdx.x * 8 + (threadIdx.x >> 5);
  int lane = threadIdx.x & 31;
  int r0 = gw * 2;
  const float4* x0 = reinterpret_cast<const float4*>(g_xs + (size_t)r0 * DI) + lane * 4;
  const float4* x1 = reinterpret_cast<const float4*>(g_xs + (size_t)(r0 + 1) * DI) + lane * 4;
  float4 v0[4], v1[4];
#pragma unroll
  for (int j = 0; j < 4; ++j) { v0[j] = x0[j]; v1[j] = x1[j]; }
  float* o0 = g_dbc + (size_t)r0 * 48;
  float* o1 = o0 + 48;
  for (int n = 0; n < 48; ++n) {
    const float4* w = reinterpret_cast<const float4*>(xpw + (size_t)n * DI) + lane * 4;
    float a0 = 0.f, a1 = 0.f;
#pragma unroll
    for (int j = 0; j < 4; ++j) {
      float4 wv = w[j];
      a0 = fmaf(v0[j].x, wv.x, a0); a0 = fmaf(v0[j].y, wv.y, a0);
      a0 = fmaf(v0[j].z, wv.z, a0); a0 = fmaf(v0[j].w, wv.w, a0);
      a1 = fmaf(v1[j].x, wv.x, a1); a1 = fmaf(v1[j].y, wv.y, a1);
      a1 = fmaf(v1[j].z, wv.z, a1); a1 = fmaf(v1[j].w, wv.w, a1);
    }
#pragma unroll
    for (int o = 16; o; o >>= 1) {
      a0 += __shfl_xor_sync(0xffffffffu, a0, o);
      a1 += __shfl_xor_sync(0xffffffffu, a1, o);
    }
    if (lane == 0) { o0[n] = a0; o1[n] = a1; }
  }
}

// ---------------- dt = softplus(dbc[:, :16] @ dt_w^T + dt_b) ---------------
__global__ void k_dt(const float* __restrict__ dtw, const float* __restrict__ dtb) {
  int idx = blockIdx.x * blockDim.x + threadIdx.x;
  int d   = idx & (DI - 1);
  int row = idx >> 9;
  const float* r = g_dbc + (size_t)row * 48;
  const float* w = dtw + (size_t)d * DTR;
  float acc = dtb[d];
#pragma unroll
  for (int k = 0; k < DTR; ++k) acc = fmaf(r[k], w[k], acc);
  g_dt[idx] = (acc > 20.f) ? acc : log1pf(__expf(acc));
}

// ---------------- selective scan: cp.async tile pipeline --------------------
// block = (b, 64-d chunk), 1024 threads (64 d x 16 s). Tiles of T=8 steps,
// triple-buffered smem; global loads fully decoupled from serial chain.
constexpr int SCT = 8;     // steps per tile
constexpr int SCS = 3;     // stages
__global__ void __launch_bounds__(1024) k_scan(const float* __restrict__ A_log,
                                               const float* __restrict__ Dp) {
  __shared__ __align__(16) float sdt[SCS][SCT][64];
  __shared__ __align__(16) float sxs[SCS][SCT][64];
  __shared__ __align__(16) float szg[SCS][SCT][64];
  __shared__ __align__(16) float sB [SCS][SCT][16];
  __shared__ __align__(16) float sC [SCS][SCT][16];

  const int tid = threadIdx.x;
  const int b  = blockIdx.x >> 3;
  const int dc = blockIdx.x & 7;
  const int s  = tid & 15;
  const int dl = tid >> 4;          // 0..63
  const int d  = dc * 64 + dl;
  const float a  = -expf(A_log[d * DS + s]);
  const float dp = Dp[d];
  const size_t rowbase = (size_t)b * L;

  // cp.async source bases
  const float* gdt = g_dt  + rowbase * DI + dc * 64;
  const float* gxs = g_xs  + rowbase * DI + dc * 64;
  const float* gzg = g_xz  + rowbase * (2 * DI) + DI + dc * 64;
  const float* gB  = g_dbc + rowbase * 48 + 16;
  const float* gC  = g_dbc + rowbase * 48 + 32;

  auto issue = [&](int tile, int st) {
    int t0 = tile * SCT;
    if (tid < 128) {            // dt: 8 rows x 16 chunks
      int r = tid >> 4, c = tid & 15;
      cp16(smem_u32(&sdt[st][r][c * 4]), gdt + (size_t)(t0 + r) * DI + c * 4);
    } else if (tid < 256) {     // xs
      int q = tid - 128, r = q >> 4, c = q & 15;
      cp16(smem_u32(&sxs[st][r][c * 4]), gxs + (size_t)(t0 + r) * DI + c * 4);
    } else if (tid < 384) {     // zg
      int q = tid - 256, r = q >> 4, c = q & 15;
      cp16(smem_u32(&szg[st][r][c * 4]), gzg + (size_t)(t0 + r) * (2 * DI) + c * 4);
    } else if (tid < 416) {     // B: 8 rows x 4 chunks
      int q = tid - 384, r = q >> 2, c = q & 3;
      cp16(smem_u32(&sB[st][r][c * 4]), gB + (size_t)(t0 + r) * 48 + c * 4);
    } else if (tid < 448) {     // C
      int q = tid - 416, r = q >> 2, c = q & 3;
      cp16(smem_u32(&sC[st][r][c * 4]), gC + (size_t)(t0 + r) * 48 + c * 4);
    }
    cp_commit();
  };

  float h = 0.f;
  __nv_bfloat16* pyh = g_yh + rowbase * DI + d;
  __nv_bfloat16* pyl = g_yl + rowbase * DI + d;

  constexpr int NT = L / SCT;   // 128 tiles
  issue(0, 0);
  issue(1, 1);
  for (int i = 0; i < NT; ++i) {
    cp_wait<1>();
    __syncthreads();
    if (i + 2 < NT) issue(i + 2, (i + 2) % SCS);
    int st = i % SCS;
#pragma unroll
    for (int t = 0; t < SCT; ++t) {
      float dtv = sdt[st][t][dl];
      float xv  = sxs[st][t][dl];
      float Bv  = sB [st][t][s];
      float Cv  = sC [st][t][s];
      float e = __expf(dtv * a);
      h = fmaf(e, h, dtv * xv * Bv);
      float val = h * Cv;
#pragma unroll
      for (int o = 8; o; o >>= 1)
        val += __shfl_xor_sync(0xffffffffu, val, o, 16);
      if (s == 0) {
        float zg = szg[st][t][dl];
        float vy = (val + xv * dp) * siluf(zg);
        __nv_bfloat16 hb = __float2bfloat16_rn(vy);
        size_t off = (size_t)(i * SCT + t) * DI;
        pyh[off] = hb;
        pyl[off] = __float2bfloat16_rn(vy - __bfloat162float(hb));
      }
    }
    __syncthreads();
  }
}

// ---------------- launch ----------------------------------------------------
extern "C" void kernel_launch(void* const* d_in, const int* in_sizes, int n_in,
                              void* d_out, int out_size) {
  const float* z      = (const float*)d_in[0];
  const float* lg     = (const float*)d_in[1];
  const float* lb     = (const float*)d_in[2];
  const float* lw     = (const float*)d_in[3];
  const float* lbias  = (const float*)d_in[4];
  const float* temb   = (const float*)d_in[5];
  const float* ln_g   = (const float*)d_in[6];
  const float* ln_b   = (const float*)d_in[7];
  const float* in_w   = (const float*)d_in[8];
  const float* in_b   = (const float*)d_in[9];
  const float* conv_w = (const float*)d_in[10];
  const float* conv_b = (const float*)d_in[11];
  const float* xp_w   = (const float*)d_in[12];
  const float* dt_w   = (const float*)d_in[13];
  const float* dt_b   = (const float*)d_in[14];
  const float* A_log  = (const float*)d_in[15];
  const float* Dp     = (const float*)d_in[16];
  const float* out_w  = (const float*)d_in[17];
  const float* out_b  = (const float*)d_in[18];
  const float* on_g   = (const float*)d_in[19];
  const float* on_b   = (const float*)d_in[20];
  const float* op_w   = (const float*)d_in[21];
  const float* op_b   = (const float*)d_in[22];
  float* out = (float*)d_out;

  float *p_h, *p_xn, *p_xz;
  __nv_bfloat16 *p_xnh, *p_xnl, *p_yh, *p_yl, *p_wih, *p_wil, *p_woh, *p_wol;
  cudaGetSymbolAddress((void**)&p_h,   g_h);
  cudaGetSymbolAddress((void**)&p_xn,  g_xn);
  cudaGetSymbolAddress((void**)&p_xz,  g_xz);
  cudaGetSymbolAddress((void**)&p_xnh, g_xnh);
  cudaGetSymbolAddress((void**)&p_xnl, g_xnl);
  cudaGetSymbolAddress((void**)&p_yh,  g_yh);
  cudaGetSymbolAddress((void**)&p_yl,  g_yl);
  cudaGetSymbolAddress((void**)&p_wih, g_wih);
  cudaGetSymbolAddress((void**)&p_wil, g_wil);
  cudaGetSymbolAddress((void**)&p_woh, g_woh);
  cudaGetSymbolAddress((void**)&p_wol, g_wol);

  cudaFuncSetAttribute(hmma_gemm<false>,
                       cudaFuncAttributeMaxDynamicSharedMemorySize, SMEM_H);
  cudaFuncSetAttribute(hmma_gemm<true>,
                       cudaFuncAttributeMaxDynamicSharedMemorySize, SMEM_H);

  const int NIW = NL * 2 * DI * D, NOW = NL * D * DI;
  k_cvt<<<(NIW + 255) / 256, 256>>>(in_w, p_wih, p_wil, NIW);
  k_cvt<<<(NOW + 255) / 256, 256>>>(out_w, p_woh, p_wol, NOW);

  k_base<<<B, LAT>>>(z, lg, lb, lw, lbias);
  k_fillh<<<NR * D / 256, 256>>>(temb);

  for (int i = 0; i < NL; ++i) {
    k_ln_t<true><<<NR / 8, 256>>>(p_h, ln_g + i * D, ln_b + i * D, nullptr,
                                  p_xnh, p_xnl);
    hmma_gemm<false><<<dim3(8, NR / 128), 256, SMEM_H>>>(
        p_xnh, p_xnl, p_wih + (size_t)i * 2 * DI * D,
        p_wil + (size_t)i * 2 * DI * D, in_b + i * 2 * DI, p_xz, 2 * DI, D);
    k_conv<<<NR * DI / 4 / 256, 256>>>(conv_w + i * DI * KC, conv_b + i * DI);
    k_dbc<<<NR / 16, 256>>>(xp_w + (size_t)i * 48 * DI);
    k_dt<<<NR * DI / 256, 256>>>(dt_w + i * DI * DTR, dt_b + i * DI);
    k_scan<<<B * 8, 1024>>>(A_log + i * DI * DS, Dp + i * DI);
    hmma_gemm<true><<<dim3(2, NR / 128), 256, SMEM_H>>>(
        p_yh, p_yl, p_woh + (size_t)i * D * DI, p_wol + (size_t)i * D * DI,
        out_b + i * D, p_h, D, DI);
  }

  k_ln_t<false><<<NR / 8, 256>>>(p_h, on_g, on_b, p_xn, nullptr, nullptr);
  sgemm_nt<128, 64, 8, 8, 4>
      <<<dim3(1, NR / 128), 256>>>(p_xn, op_w, op_b, out, NR, OUTD, D);
}

// round 5
// speedup vs baseline: 1.8386x; 1.0752x over previous
#include <cuda_runtime.h>
#include <cuda_fp16.h>
#include <math.h>
#include <stdint.h>

namespace {
constexpr int B  = 16,  LAT = 256, D  = 256, DI = 512, DS = 16, DTR = 16;
constexpr int L  = 1024, KC = 4,  OUTD = 64, NL = 4;
constexpr int NR = B * L;  // 16384 rows of (b, t)
}

// ---------------- scratch (static device globals; no allocation) ----------
__device__ float g_h   [NR * D];
__device__ float g_xn  [NR * D];
__device__ float g_xz  [NR * 2 * DI];
__device__ float g_xs  [NR * DI];
__device__ float g_dbc [NR * 48];
__device__ float g_dt  [NR * DI];
__device__ float g_base[B * D];
// split-fp16 activations (hi+lo), single-fp16 weights
__device__ __half g_xnh[NR * D],  g_xnl[NR * D];
__device__ __half g_yh [NR * DI], g_yl [NR * DI];
__device__ __half g_wi [NL * 2 * DI * D];
__device__ __half g_wo [NL * D * DI];

// ---------------- PTX helpers ----------------------------------------------
__device__ __forceinline__ uint32_t smem_u32(const void* p) {
  uint32_t a;
  asm("{ .reg .u64 t; cvta.to.shared.u64 t, %1; cvt.u32.u64 %0, t; }"
      : "=r"(a) : "l"(p));
  return a;
}
__device__ __forceinline__ void cp16(uint32_t dst, const void* src) {
  asm volatile("cp.async.cg.shared.global [%0], [%1], 16;" ::"r"(dst),
               "l"(src));
}
__device__ __forceinline__ void cp_commit() {
  asm volatile("cp.async.commit_group;" ::: "memory");
}
template <int N>
__device__ __forceinline__ void cp_wait() {
  asm volatile("cp.async.wait_group %0;" ::"n"(N) : "memory");
}
__device__ __forceinline__ void ldsm4(uint32_t (&r)[4], uint32_t addr) {
  asm volatile(
      "ldmatrix.sync.aligned.m8n8.x4.shared.b16 {%0,%1,%2,%3}, [%4];"
      : "=r"(r[0]), "=r"(r[1]), "=r"(r[2]), "=r"(r[3])
      : "r"(addr));
}
__device__ __forceinline__ void mma16816(float (&d)[4], const uint32_t (&a)[4],
                                         uint32_t b0, uint32_t b1) {
  asm volatile(
      "mma.sync.aligned.m16n8k16.row.col.f32.f16.f16.f32 "
      "{%0,%1,%2,%3}, {%4,%5,%6,%7}, {%8,%9}, {%0,%1,%2,%3};"
      : "+f"(d[0]), "+f"(d[1]), "+f"(d[2]), "+f"(d[3])
      : "r"(a[0]), "r"(a[1]), "r"(a[2]), "r"(a[3]), "r"(b0), "r"(b1));
}

// ---------------- math helpers ---------------------------------------------
__device__ __forceinline__ float geluf(float x) {
  return 0.5f * x * (1.f + erff(x * 0.70710678118654752f));
}
__device__ __forceinline__ float siluf(float x) {
  return x / (1.f + __expf(-x));
}
__device__ __forceinline__ float blk_sum_256(float v, float* red) {
  __syncthreads();
  int lane = threadIdx.x & 31, w = threadIdx.x >> 5;
#pragma unroll
  for (int o = 16; o; o >>= 1) v += __shfl_xor_sync(0xffffffffu, v, o);
  if (lane == 0) red[w] = v;
  __syncthreads();
  if (threadIdx.x < 32) {
    float t = (threadIdx.x < 8) ? red[threadIdx.x] : 0.f;
#pragma unroll
    for (int o = 4; o; o >>= 1) t += __shfl_xor_sync(0xffffffffu, t, o);
    if (threadIdx.x == 0) red[0] = t;
  }
  __syncthreads();
  return red[0];
}

// ---------------- HMMA GEMM: C = (Ah+Al)@Bw^T + bias [+C], fp16 ------------
// A split into fp16 hi+lo (22 mantissa bits); weights single fp16.
constexpr int LDSE   = 40;
constexpr int ARR_B  = 128 * LDSE * 2;   // 10240 B
constexpr int STG_B  = 3 * ARR_B;        // 30720 B
constexpr int SMEM_H = 2 * STG_B;        // 61440 B

template <bool ACCUM>
__global__ void __launch_bounds__(256, 2)
hmma_gemm(const __half* __restrict__ Ah, const __half* __restrict__ Al,
          const __half* __restrict__ Bw, const float* __restrict__ bias,
          float* __restrict__ C, int N, int K) {
  extern __shared__ char smem[];
  const uint32_t sb = smem_u32(smem);
  const int tid = threadIdx.x, lane = tid & 31, wid = tid >> 5;
  const int wm = wid >> 1, wn = wid & 1;
  const int m0 = blockIdx.y * 128, n0 = blockIdx.x * 128;

  float acc[2][8][4] = {};
  const int nchunk = K >> 5;

  auto issue = [&](int s, int k0) {
    uint32_t st = sb + s * STG_B;
#pragma unroll
    for (int i = 0; i < 2; ++i) {
      int seg = tid + i * 256;
      int r = seg >> 2, c4 = seg & 3;
      uint32_t so = r * (LDSE * 2) + c4 * 16;
      size_t goA = (size_t)(m0 + r) * K + k0 + c4 * 8;
      size_t goB = (size_t)(n0 + r) * K + k0 + c4 * 8;
      cp16(st + 0 * ARR_B + so, Ah + goA);
      cp16(st + 1 * ARR_B + so, Al + goA);
      cp16(st + 2 * ARR_B + so, Bw + goB);
    }
    cp_commit();
  };

  auto compute = [&](int s) {
    uint32_t st = sb + s * STG_B;
#pragma unroll
    for (int ks = 0; ks < 32; ks += 16) {
      uint32_t aH[2][4], aL[2][4];
#pragma unroll
      for (int mi = 0; mi < 2; ++mi) {
        uint32_t ro = wm * 32 + mi * 16 + (lane & 15);
        uint32_t co = ks + ((lane >> 4) & 1) * 8;
        uint32_t ad = st + (ro * LDSE + co) * 2;
        ldsm4(aH[mi], ad);
        ldsm4(aL[mi], ad + ARR_B);
      }
#pragma unroll
      for (int p = 0; p < 4; ++p) {
        uint32_t bh[4];
        uint32_t nr = wn * 64 + p * 16 + (lane & 7) + ((lane >> 4) & 1) * 8;
        uint32_t kc = ks + ((lane >> 3) & 1) * 8;
        uint32_t ad = st + 2 * ARR_B + (nr * LDSE + kc) * 2;
        ldsm4(bh, ad);
#pragma unroll
        for (int mi = 0; mi < 2; ++mi) {
#pragma unroll
          for (int q = 0; q < 2; ++q) {
            mma16816(acc[mi][p * 2 + q], aH[mi], bh[q * 2], bh[q * 2 + 1]);
            mma16816(acc[mi][p * 2 + q], aL[mi], bh[q * 2], bh[q * 2 + 1]);
          }
        }
      }
    }
  };

  issue(0, 0);
  for (int c = 0; c < nchunk; ++c) {
    if (c + 1 < nchunk) {
      issue((c + 1) & 1, (c + 1) * 32);
      cp_wait<1>();
    } else {
      cp_wait<0>();
    }
    __syncthreads();
    compute(c & 1);
    __syncthreads();
  }

  const int mb = m0 + wm * 32 + (lane >> 2);
  const int nb = n0 + wn * 64 + (lane & 3) * 2;
#pragma unroll
  for (int mi = 0; mi < 2; ++mi) {
#pragma unroll
    for (int ni = 0; ni < 8; ++ni) {
      int c = nb + ni * 8;
      float b0 = bias[c], b1 = bias[c + 1];
      float* p0 = C + (size_t)(mb + mi * 16) * N + c;
      float* p1 = C + (size_t)(mb + mi * 16 + 8) * N + c;
      float2 v0 = make_float2(acc[mi][ni][0] + b0, acc[mi][ni][1] + b1);
      float2 v1 = make_float2(acc[mi][ni][2] + b0, acc[mi][ni][3] + b1);
      if (ACCUM) {
        float2 o0 = *reinterpret_cast<float2*>(p0);
        float2 o1 = *reinterpret_cast<float2*>(p1);
        v0.x += o0.x; v0.y += o0.y; v1.x += o1.x; v1.y += o1.y;
      }
      *reinterpret_cast<float2*>(p0) = v0;
      *reinterpret_cast<float2*>(p1) = v1;
    }
  }
}

// ---------------- weights fp32 -> fp16 (both arrays, one kernel) -----------
__global__ void k_cvt_all(const float* __restrict__ in_w,
                          const float* __restrict__ out_w) {
  const int NIW = NL * 2 * DI * D, NOW = NL * D * DI;
  int i = blockIdx.x * blockDim.x + threadIdx.x;
  if (i < NIW) {
    g_wi[i] = __float2half_rn(in_w[i]);
  } else if (i < NIW + NOW) {
    g_wo[i - NIW] = __float2half_rn(out_w[i - NIW]);
  }
}

// ---------------- base = gelu(LN(z) @ lw.T + bias) -------------------------
__global__ void k_base(const float* __restrict__ z, const float* __restrict__ lg,
                       const float* __restrict__ lb, const float* __restrict__ lw,
                       const float* __restrict__ lbias) {
  __shared__ float xn[LAT];
  __shared__ float red[32];
  int b = blockIdx.x, tid = threadIdx.x;
  float v  = z[b * LAT + tid];
  float mu = blk_sum_256(v, red) * (1.f / LAT);
  float dv = v - mu;
  float var = blk_sum_256(dv * dv, red) * (1.f / LAT);
  float inv = rsqrtf(var + 1e-5f);
  xn[tid] = dv * inv * lg[tid] + lb[tid];
  __syncthreads();
  float acc = lbias[tid];
  const float* wr = lw + tid * LAT;
#pragma unroll 8
  for (int k = 0; k < LAT; ++k) acc = fmaf(xn[k], wr[k], acc);
  g_base[b * D + tid] = geluf(acc);
}

// ---------------- layer-0: h = base + temb, then LN -> split fp16 ----------
__global__ void k_ln0(const float* __restrict__ temb, const float* __restrict__ g,
                      const float* __restrict__ be) {
  int row  = blockIdx.x * 8 + (threadIdx.x >> 5);
  int lane = threadIdx.x & 31;
  int b = row >> 10, t = row & (L - 1);
  float v[8];
  float s = 0.f;
#pragma unroll
  for (int j = 0; j < 8; ++j) {
    int c = lane + 32 * j;
    v[j] = g_base[b * D + c] + temb[t * D + c];
    g_h[(size_t)row * D + c] = v[j];
    s += v[j];
  }
#pragma unroll
  for (int o2 = 16; o2; o2 >>= 1) s += __shfl_xor_sync(0xffffffffu, s, o2);
  float mu = s * (1.f / D);
  float s2 = 0.f;
#pragma unroll
  for (int j = 0; j < 8; ++j) { float dv = v[j] - mu; s2 += dv * dv; }
#pragma unroll
  for (int o2 = 16; o2; o2 >>= 1) s2 += __shfl_xor_sync(0xffffffffu, s2, o2);
  float inv = rsqrtf(s2 * (1.f / D) + 1e-5f);
#pragma unroll
  for (int j = 0; j < 8; ++j) {
    int c = lane + 32 * j;
    float r = (v[j] - mu) * inv * g[c] + be[c];
    __half hi = __float2half_rn(r);
    g_xnh[(size_t)row * D + c] = hi;
    g_xnl[(size_t)row * D + c] = __float2half_rn(r - __half2float(hi));
  }
}

// ---------------- LayerNorm (warp per row) ---------------------------------
template <bool HF>
__global__ void k_ln_t(const float* __restrict__ x, const float* __restrict__ g,
                       const float* __restrict__ be, float* __restrict__ o,
                       __half* __restrict__ oh, __half* __restrict__ ol) {
  int row  = blockIdx.x * 8 + (threadIdx.x >> 5);
  int lane = threadIdx.x & 31;
  const float* xr = x + (size_t)row * D;
  float v[8];
  float s = 0.f;
#pragma unroll
  for (int j = 0; j < 8; ++j) { v[j] = xr[lane + 32 * j]; s += v[j]; }
#pragma unroll
  for (int o2 = 16; o2; o2 >>= 1) s += __shfl_xor_sync(0xffffffffu, s, o2);
  float mu = s * (1.f / D);
  float s2 = 0.f;
#pragma unroll
  for (int j = 0; j < 8; ++j) { float dv = v[j] - mu; s2 += dv * dv; }
#pragma unroll
  for (int o2 = 16; o2; o2 >>= 1) s2 += __shfl_xor_sync(0xffffffffu, s2, o2);
  float inv = rsqrtf(s2 * (1.f / D) + 1e-5f);
#pragma unroll
  for (int j = 0; j < 8; ++j) {
    int c = lane + 32 * j;
    float r = (v[j] - mu) * inv * g[c] + be[c];
    if (HF) {
      __half hi = __float2half_rn(r);
      oh[(size_t)row * D + c] = hi;
      ol[(size_t)row * D + c] = __float2half_rn(r - __half2float(hi));
    } else {
      o[(size_t)row * D + c] = r;
    }
  }
}

// ---------------- SGEMM (fp32, small final GEMM only) ----------------------
template <int BM, int BN, int BK, int TM, int TN>
__global__ void __launch_bounds__((BM / TM) * (BN / TN))
sgemm_nt(const float* __restrict__ A, const float* __restrict__ Bm,
         const float* __restrict__ bias, float* __restrict__ C,
         int M, int N, int K) {
  constexpr int NT = (BM / TM) * (BN / TN);
  __shared__ float As[BK][BM];
  __shared__ float Bs[BK][BN];
  int tid = threadIdx.x;
  int bn = blockIdx.x, bm = blockIdx.y;
  const float* Ab = A  + (size_t)bm * BM * K;
  const float* Bb = Bm + (size_t)bn * BN * K;
  int tx = tid % (BN / TN), ty = tid / (BN / TN);
  float acc[TM][TN] = {};
  for (int k0 = 0; k0 < K; k0 += BK) {
    for (int i = tid * 4; i < BM * BK; i += NT * 4) {
      int r = i / BK, c = i % BK;
      float4 v = *reinterpret_cast<const float4*>(Ab + (size_t)r * K + k0 + c);
      As[c + 0][r] = v.x; As[c + 1][r] = v.y; As[c + 2][r] = v.z; As[c + 3][r] = v.w;
    }
    for (int i = tid * 4; i < BN * BK; i += NT * 4) {
      int r = i / BK, c = i % BK;
      float4 v = *reinterpret_cast<const float4*>(Bb + (size_t)r * K + k0 + c);
      Bs[c + 0][r] = v.x; Bs[c + 1][r] = v.y; Bs[c + 2][r] = v.z; Bs[c + 3][r] = v.w;
    }
    __syncthreads();
#pragma unroll
    for (int k = 0; k < BK; ++k) {
      float ra[TM], rb[TN];
#pragma unroll
      for (int i = 0; i < TM; ++i) ra[i] = As[k][ty * TM + i];
#pragma unroll
      for (int j = 0; j < TN; ++j) rb[j] = Bs[k][tx * TN + j];
#pragma unroll
      for (int i = 0; i < TM; ++i)
#pragma unroll
        for (int j = 0; j < TN; ++j) acc[i][j] = fmaf(ra[i], rb[j], acc[i][j]);
    }
    __syncthreads();
  }
#pragma unroll
  for (int i = 0; i < TM; ++i) {
    int m = bm * BM + ty * TM + i;
    float* Cr = C + (size_t)m * N + bn * BN + tx * TN;
#pragma unroll
    for (int j = 0; j < TN; ++j) Cr[j] = acc[i][j] + bias[bn * BN + tx * TN + j];
  }
}

// ---------------- depthwise causal conv (K=4) + silu, float4 ---------------
__global__ void k_conv(const float* __restrict__ w, const float* __restrict__ cb) {
  int idx = blockIdx.x * blockDim.x + threadIdx.x;  // NR*DI/4
  int d4 = idx & (DI / 4 - 1);
  int t  = (idx >> 7) & (L - 1);
  int b  = idx >> 17;
  int d  = d4 * 4;
  const float* base = g_xz + (size_t)(b * L) * (2 * DI) + d;
  float4 wv[KC];
#pragma unroll
  for (int k = 0; k < KC; ++k) {
    wv[k].x = w[(d + 0) * KC + k];
    wv[k].y = w[(d + 1) * KC + k];
    wv[k].z = w[(d + 2) * KC + k];
    wv[k].w = w[(d + 3) * KC + k];
  }
  float4 acc = *reinterpret_cast<const float4*>(cb + d);
#pragma unroll
  for (int k = 0; k < KC; ++k) {
    int tt = t + k - (KC - 1);
    if (tt >= 0) {
      float4 x = *reinterpret_cast<const float4*>(base + (size_t)tt * (2 * DI));
      acc.x = fmaf(x.x, wv[k].x, acc.x);
      acc.y = fmaf(x.y, wv[k].y, acc.y);
      acc.z = fmaf(x.z, wv[k].z, acc.z);
      acc.w = fmaf(x.w, wv[k].w, acc.w);
    }
  }
  float4 o;
  o.x = siluf(acc.x); o.y = siluf(acc.y); o.z = siluf(acc.z); o.w = siluf(acc.w);
  *reinterpret_cast<float4*>(g_xs + (size_t)idx * 4) = o;
}

// ---------------- dbc = xs @ xp_w^T (N=48): 2 rows/warp, float4 ------------
__global__ void __launch_bounds__(256) k_dbc(const float* __restrict__ xpw) {
  int gw   = blockIdx.x * 8 + (threadIdx.x >> 5);
  int lane = threadIdx.x & 31;
  int r0 = gw * 2;
  const float4* x0 = reinterpret_cast<const float4*>(g_xs + (size_t)r0 * DI) + lane * 4;
  const float4* x1 = reinterpret_cast<const float4*>(g_xs + (size_t)(r0 + 1) * DI) + lane * 4;
  float4 v0[4], v1[4];
#pragma unroll
  for (int j = 0; j < 4; ++j) { v0[j] = x0[j]; v1[j] = x1[j]; }
  float* o0 = g_dbc + (size_t)r0 * 48;
  float* o1 = o0 + 48;
  for (int n = 0; n < 48; ++n) {
    const float4* w = reinterpret_cast<const float4*>(xpw + (size_t)n * DI) + lane * 4;
    float a0 = 0.f, a1 = 0.f;
#pragma unroll
    for (int j = 0; j < 4; ++j) {
      float4 wv = w[j];
      a0 = fmaf(v0[j].x, wv.x, a0); a0 = fmaf(v0[j].y, wv.y, a0);
      a0 = fmaf(v0[j].z, wv.z, a0); a0 = fmaf(v0[j].w, wv.w, a0);
      a1 = fmaf(v1[j].x, wv.x, a1); a1 = fmaf(v1[j].y, wv.y, a1);
      a1 = fmaf(v1[j].z, wv.z, a1); a1 = fmaf(v1[j].w, wv.w, a1);
    }
#pragma unroll
    for (int o = 16; o; o >>= 1) {
      a0 += __shfl_xor_sync(0xffffffffu, a0, o);
      a1 += __shfl_xor_sync(0xffffffffu, a1, o);
    }
    if (lane == 0) { o0[n] = a0; o1[n] = a1; }
  }
}

// ---------------- dt = softplus(dbc[:, :16] @ dt_w^T + dt_b) ---------------
__global__ void k_dt(const float* __restrict__ dtw, const float* __restrict__ dtb) {
  int idx = blockIdx.x * blockDim.x + threadIdx.x;
  int d   = idx & (DI - 1);
  int row = idx >> 9;
  const float* r = g_dbc + (size_t)row * 48;
  const float* w = dtw + (size_t)d * DTR;
  float acc = dtb[d];
#pragma unroll
  for (int k = 0; k < DTR; ++k) acc = fmaf(r[k], w[k], acc);
  g_dt[idx] = (acc > 20.f) ? acc : log1pf(__expf(acc));
}

// ---------------- selective scan: cp.async tile pipeline --------------------
constexpr int SCT = 8;
constexpr int SCS = 3;
__global__ void __launch_bounds__(1024) k_scan(const float* __restrict__ A_log,
                                               const float* __restrict__ Dp) {
  __shared__ __align__(16) float sdt[SCS][SCT][64];
  __shared__ __align__(16) float sxs[SCS][SCT][64];
  __shared__ __align__(16) float szg[SCS][SCT][64];
  __shared__ __align__(16) float sB [SCS][SCT][16];
  __shared__ __align__(16) float sC [SCS][SCT][16];

  const int tid = threadIdx.x;
  const int b  = blockIdx.x >> 3;
  const int dc = blockIdx.x & 7;
  const int s  = tid & 15;
  const int dl = tid >> 4;
  const int d  = dc * 64 + dl;
  const float a  = -expf(A_log[d * DS + s]);
  const float dp = Dp[d];
  const size_t rowbase = (size_t)b * L;

  const float* gdt = g_dt  + rowbase * DI + dc * 64;
  const float* gxs = g_xs  + rowbase * DI + dc * 64;
  const float* gzg = g_xz  + rowbase * (2 * DI) + DI + dc * 64;
  const float* gB  = g_dbc + rowbase * 48 + 16;
  const float* gC  = g_dbc + rowbase * 48 + 32;

  auto issue = [&](int tile, int st) {
    int t0 = tile * SCT;
    if (tid < 128) {
      int r = tid >> 4, c = tid & 15;
      cp16(smem_u32(&sdt[st][r][c * 4]), gdt + (size_t)(t0 + r) * DI + c * 4);
    } else if (tid < 256) {
      int q = tid - 128, r = q >> 4, c = q & 15;
      cp16(smem_u32(&sxs[st][r][c * 4]), gxs + (size_t)(t0 + r) * DI + c * 4);
    } else if (tid < 384) {
      int q = tid - 256, r = q >> 4, c = q & 15;
      cp16(smem_u32(&szg[st][r][c * 4]), gzg + (size_t)(t0 + r) * (2 * DI) + c * 4);
    } else if (tid < 416) {
      int q = tid - 384, r = q >> 2, c = q & 3;
      cp16(smem_u32(&sB[st][r][c * 4]), gB + (size_t)(t0 + r) * 48 + c * 4);
    } else if (tid < 448) {
      int q = tid - 416, r = q >> 2, c = q & 3;
      cp16(smem_u32(&sC[st][r][c * 4]), gC + (size_t)(t0 + r) * 48 + c * 4);
    }
    cp_commit();
  };

  float h = 0.f;
  __half* pyh = g_yh + rowbase * DI + d;
  __half* pyl = g_yl + rowbase * DI + d;

  constexpr int NT = L / SCT;
  issue(0, 0);
  issue(1, 1);
  for (int i = 0; i < NT; ++i) {
    cp_wait<1>();
    __syncthreads();
    if (i + 2 < NT) issue(i + 2, (i + 2) % SCS);
    int st = i % SCS;
#pragma unroll
    for (int t = 0; t < SCT; ++t) {
      float dtv = sdt[st][t][dl];
      float xv  = sxs[st][t][dl];
      float Bv  = sB [st][t][s];
      float Cv  = sC [st][t][s];
      float e = __expf(dtv * a);
      h = fmaf(e, h, dtv * xv * Bv);
      float val = h * Cv;
#pragma unroll
      for (int o = 8; o; o >>= 1)
        val += __shfl_xor_sync(0xffffffffu, val, o, 16);
      if (s == 0) {
        float zg = szg[st][t][dl];
        float vy = (val + xv * dp) * siluf(zg);
        __half hb = __float2half_rn(vy);
        size_t off = (size_t)(i * SCT + t) * DI;
        pyh[off] = hb;
        pyl[off] = __float2half_rn(vy - __half2float(hb));
      }
    }
    __syncthreads();
  }
}

// ---------------- launch ----------------------------------------------------
extern "C" void kernel_launch(void* const* d_in, const int* in_sizes, int n_in,
                              void* d_out, int out_size) {
  const float* z      = (const float*)d_in[0];
  const float* lg     = (const float*)d_in[1];
  const float* lb     = (const float*)d_in[2];
  const float* lw     = (const float*)d_in[3];
  const float* lbias  = (const float*)d_in[4];
  const float* temb   = (const float*)d_in[5];
  const float* ln_g   = (const float*)d_in[6];
  const float* ln_b   = (const float*)d_in[7];
  const float* in_w   = (const float*)d_in[8];
  const float* in_b   = (const float*)d_in[9];
  const float* conv_w = (const float*)d_in[10];
  const float* conv_b = (const float*)d_in[11];
  const float* xp_w   = (const float*)d_in[12];
  const float* dt_w   = (const float*)d_in[13];
  const float* dt_b   = (const float*)d_in[14];
  const float* A_log  = (const float*)d_in[15];
  const float* Dp     = (const float*)d_in[16];
  const float* out_w  = (const float*)d_in[17];
  const float* out_b  = (const float*)d_in[18];
  const float* on_g   = (const float*)d_in[19];
  const float* on_b   = (const float*)d_in[20];
  const float* op_w   = (const float*)d_in[21];
  const float* op_b   = (const float*)d_in[22];
  float* out = (float*)d_out;

  float *p_h, *p_xn, *p_xz;
  __half *p_xnh, *p_xnl, *p_yh, *p_yl, *p_wi, *p_wo;
  cudaGetSymbolAddress((void**)&p_h,   g_h);
  cudaGetSymbolAddress((void**)&p_xn,  g_xn);
  cudaGetSymbolAddress((void**)&p_xz,  g_xz);
  cudaGetSymbolAddress((void**)&p_xnh, g_xnh);
  cudaGetSymbolAddress((void**)&p_xnl, g_xnl);
  cudaGetSymbolAddress((void**)&p_yh,  g_yh);
  cudaGetSymbolAddress((void**)&p_yl,  g_yl);
  cudaGetSymbolAddress((void**)&p_wi,  g_wi);
  cudaGetSymbolAddress((void**)&p_wo,  g_wo);

  cudaFuncSetAttribute(hmma_gemm<false>,
                       cudaFuncAttributeMaxDynamicSharedMemorySize, SMEM_H);
  cudaFuncSetAttribute(hmma_gemm<true>,
                       cudaFuncAttributeMaxDynamicSharedMemorySize, SMEM_H);

  const int NW = NL * 2 * DI * D + NL * D * DI;
  // launch order puts hmma_gemm at app-launch #4 (the ncu-profiled slot)
  k_cvt_all<<<(NW + 255) / 256, 256>>>(in_w, out_w);           // 1
  k_base<<<B, LAT>>>(z, lg, lb, lw, lbias);                    // 2

  for (int i = 0; i < NL; ++i) {
    if (i == 0)
      k_ln0<<<NR / 8, 256>>>(temb, ln_g, ln_b);                // 3
    else
      k_ln_t<true><<<NR / 8, 256>>>(p_h, ln_g + i * D, ln_b + i * D, nullptr,
                                    p_xnh, p_xnl);
    hmma_gemm<false><<<dim3(8, NR / 128), 256, SMEM_H>>>(      // 4 (i==0)
        p_xnh, p_xnl, p_wi + (size_t)i * 2 * DI * D, in_b + i * 2 * DI, p_xz,
        2 * DI, D);
    k_conv<<<NR * DI / 4 / 256, 256>>>(conv_w + i * DI * KC, conv_b + i * DI);
    k_dbc<<<NR / 16, 256>>>(xp_w + (size_t)i * 48 * DI);
    k_dt<<<NR * DI / 256, 256>>>(dt_w + i * DI * DTR, dt_b + i * DI);
    k_scan<<<B * 8, 1024>>>(A_log + i * DI * DS, Dp + i * DI);
    hmma_gemm<true><<<dim3(2, NR / 128), 256, SMEM_H>>>(
        p_yh, p_yl, p_wo + (size_t)i * D * DI, out_b + i * D, p_h, D, DI);
  }

  k_ln_t<false><<<NR / 8, 256>>>(p_h, on_g, on_b, p_xn, nullptr, nullptr);
  sgemm_nt<128, 64, 8, 8, 4>
      <<<dim3(1, NR / 128), 256>>>(p_xn, op_w, op_b, out, NR, OUTD, D);
}

// round 6
// speedup vs baseline: 2.9742x; 1.6177x over previous
#include <cuda_runtime.h>
#include <cuda_fp16.h>
#include <math.h>
#include <stdint.h>

namespace {
constexpr int B  = 16,  LAT = 256, D  = 256, DI = 512, DS = 16, DTR = 16;
constexpr int L  = 1024, KC = 4,  OUTD = 64, NL = 4;
constexpr int NR = B * L;
}

// ---------------- scratch ---------------------------------------------------
__device__ float g_h   [NR * D];
__device__ float g_xn  [NR * D];
__device__ float g_xz  [NR * 2 * DI];
__device__ float g_xs  [NR * DI];
__device__ float g_dbc [NR * 48];
__device__ float g_dt  [NR * DI];
__device__ float g_base[B * D];
__device__ __half g_xnh[NR * D];
__device__ __half g_yh [NR * DI];
__device__ __half g_wi [NL * 2 * DI * D];
__device__ __half g_wo [NL * D * DI];

// ---------------- PTX helpers ----------------------------------------------
__device__ __forceinline__ uint32_t smem_u32(const void* p) {
  uint32_t a;
  asm("{ .reg .u64 t; cvta.to.shared.u64 t, %1; cvt.u32.u64 %0, t; }"
      : "=r"(a) : "l"(p));
  return a;
}
__device__ __forceinline__ void cp16(uint32_t dst, const void* src) {
  asm volatile("cp.async.cg.shared.global [%0], [%1], 16;" ::"r"(dst),
               "l"(src));
}
__device__ __forceinline__ void cp_commit() {
  asm volatile("cp.async.commit_group;" ::: "memory");
}
template <int N>
__device__ __forceinline__ void cp_wait() {
  asm volatile("cp.async.wait_group %0;" ::"n"(N) : "memory");
}
__device__ __forceinline__ void ldsm4(uint32_t (&r)[4], uint32_t addr) {
  asm volatile(
      "ldmatrix.sync.aligned.m8n8.x4.shared.b16 {%0,%1,%2,%3}, [%4];"
      : "=r"(r[0]), "=r"(r[1]), "=r"(r[2]), "=r"(r[3])
      : "r"(addr));
}
__device__ __forceinline__ void mma16816(float (&d)[4], const uint32_t (&a)[4],
                                         uint32_t b0, uint32_t b1) {
  asm volatile(
      "mma.sync.aligned.m16n8k16.row.col.f32.f16.f16.f32 "
      "{%0,%1,%2,%3}, {%4,%5,%6,%7}, {%8,%9}, {%0,%1,%2,%3};"
      : "+f"(d[0]), "+f"(d[1]), "+f"(d[2]), "+f"(d[3])
      : "r"(a[0]), "r"(a[1]), "r"(a[2]), "r"(a[3]), "r"(b0), "r"(b1));
}

// ---------------- math helpers ---------------------------------------------
__device__ __forceinline__ float geluf(float x) {
  return 0.5f * x * (1.f + erff(x * 0.70710678118654752f));
}
__device__ __forceinline__ float siluf(float x) {
  return x / (1.f + __expf(-x));
}
__device__ __forceinline__ float blk_sum_256(float v, float* red) {
  __syncthreads();
  int lane = threadIdx.x & 31, w = threadIdx.x >> 5;
#pragma unroll
  for (int o = 16; o; o >>= 1) v += __shfl_xor_sync(0xffffffffu, v, o);
  if (lane == 0) red[w] = v;
  __syncthreads();
  if (threadIdx.x < 32) {
    float t = (threadIdx.x < 8) ? red[threadIdx.x] : 0.f;
#pragma unroll
    for (int o = 4; o; o >>= 1) t += __shfl_xor_sync(0xffffffffu, t, o);
    if (threadIdx.x == 0) red[0] = t;
  }
  __syncthreads();
  return red[0];
}

// ---------------- HMMA GEMM: C = A@B^T + bias [+C], plain fp16 -------------
constexpr int LDSE   = 40;
constexpr int ARR_B  = 128 * LDSE * 2;   // 10240 B
constexpr int STG_B  = 2 * ARR_B;        // 20480 B
constexpr int NSTG   = 3;
constexpr int SMEM_H = NSTG * STG_B;     // 61440 B

template <bool ACCUM>
__global__ void __launch_bounds__(256, 2)
hmma_gemm(const __half* __restrict__ Ah, const __half* __restrict__ Bw,
          const float* __restrict__ bias, float* __restrict__ C,
          int N, int K) {
  extern __shared__ char smem[];
  const uint32_t sb = smem_u32(smem);
  const int tid = threadIdx.x, lane = tid & 31, wid = tid >> 5;
  const int wm = wid >> 1, wn = wid & 1;
  const int m0 = blockIdx.y * 128, n0 = blockIdx.x * 128;

  float acc[2][8][4] = {};
  const int nchunk = K >> 5;

  auto issue = [&](int s, int k0) {
    uint32_t st = sb + s * STG_B;
#pragma unroll
    for (int i = 0; i < 2; ++i) {
      int seg = tid + i * 256;
      int r = seg >> 2, c4 = seg & 3;
      uint32_t so = r * (LDSE * 2) + c4 * 16;
      cp16(st + 0 * ARR_B + so, Ah + (size_t)(m0 + r) * K + k0 + c4 * 8);
      cp16(st + 1 * ARR_B + so, Bw + (size_t)(n0 + r) * K + k0 + c4 * 8);
    }
    cp_commit();
  };

  auto compute = [&](int s) {
    uint32_t st = sb + s * STG_B;
#pragma unroll
    for (int ks = 0; ks < 32; ks += 16) {
      uint32_t aH[2][4];
#pragma unroll
      for (int mi = 0; mi < 2; ++mi) {
        uint32_t ro = wm * 32 + mi * 16 + (lane & 15);
        uint32_t co = ks + ((lane >> 4) & 1) * 8;
        ldsm4(aH[mi], st + (ro * LDSE + co) * 2);
      }
#pragma unroll
      for (int p = 0; p < 4; ++p) {
        uint32_t bh[4];
        uint32_t nr = wn * 64 + p * 16 + (lane & 7) + ((lane >> 4) & 1) * 8;
        uint32_t kc = ks + ((lane >> 3) & 1) * 8;
        ldsm4(bh, st + 1 * ARR_B + (nr * LDSE + kc) * 2);
#pragma unroll
        for (int mi = 0; mi < 2; ++mi)
#pragma unroll
          for (int q = 0; q < 2; ++q)
            mma16816(acc[mi][p * 2 + q], aH[mi], bh[q * 2], bh[q * 2 + 1]);
      }
    }
  };

  issue(0, 0);
  if (nchunk > 1) issue(1, 32);
  for (int c = 0; c < nchunk; ++c) {
    cp_wait<1>();
    __syncthreads();
    if (c + 2 < nchunk) issue((c + 2) % NSTG, (c + 2) * 32);
    compute(c % NSTG);
    __syncthreads();
  }

  const int mb = m0 + wm * 32 + (lane >> 2);
  const int nb = n0 + wn * 64 + (lane & 3) * 2;
#pragma unroll
  for (int mi = 0; mi < 2; ++mi) {
#pragma unroll
    for (int ni = 0; ni < 8; ++ni) {
      int c = nb + ni * 8;
      float b0 = bias[c], b1 = bias[c + 1];
      float* p0 = C + (size_t)(mb + mi * 16) * N + c;
      float* p1 = C + (size_t)(mb + mi * 16 + 8) * N + c;
      float2 v0 = make_float2(acc[mi][ni][0] + b0, acc[mi][ni][1] + b1);
      float2 v1 = make_float2(acc[mi][ni][2] + b0, acc[mi][ni][3] + b1);
      if (ACCUM) {
        float2 o0 = *reinterpret_cast<float2*>(p0);
        float2 o1 = *reinterpret_cast<float2*>(p1);
        v0.x += o0.x; v0.y += o0.y; v1.x += o1.x; v1.y += o1.y;
      }
      *reinterpret_cast<float2*>(p0) = v0;
      *reinterpret_cast<float2*>(p1) = v1;
    }
  }
}

// ---------------- k_prep: weight cvt + base (fused) ------------------------
__global__ void k_prep(const float* __restrict__ in_w,
                       const float* __restrict__ out_w,
                       const float* __restrict__ z, const float* __restrict__ lg,
                       const float* __restrict__ lb, const float* __restrict__ lw,
                       const float* __restrict__ lbias) {
  __shared__ float xn[LAT];
  __shared__ float red[32];
  if (blockIdx.x < B) {
    int b = blockIdx.x, tid = threadIdx.x;
    float v  = z[b * LAT + tid];
    float mu = blk_sum_256(v, red) * (1.f / LAT);
    float dv = v - mu;
    float var = blk_sum_256(dv * dv, red) * (1.f / LAT);
    float inv = rsqrtf(var + 1e-5f);
    xn[tid] = dv * inv * lg[tid] + lb[tid];
    __syncthreads();
    float acc = lbias[tid];
    const float* wr = lw + tid * LAT;
#pragma unroll 8
    for (int k = 0; k < LAT; ++k) acc = fmaf(xn[k], wr[k], acc);
    g_base[b * D + tid] = geluf(acc);
  } else {
    const int NIW = NL * 2 * DI * D, NOW = NL * D * DI;
    int i = (blockIdx.x - B) * 256 + threadIdx.x;
    if (i < NIW) g_wi[i] = __float2half_rn(in_w[i]);
    else if (i < NIW + NOW) g_wo[i - NIW] = __float2half_rn(out_w[i - NIW]);
  }
}

// ---------------- layer-0 LN: h = base + temb -> LN -> fp16 ----------------
__global__ void k_ln0(const float* __restrict__ temb, const float* __restrict__ g,
                      const float* __restrict__ be) {
  int row  = blockIdx.x * 8 + (threadIdx.x >> 5);
  int lane = threadIdx.x & 31;
  int b = row >> 10, t = row & (L - 1);
  float v[8];
  float s = 0.f;
#pragma unroll
  for (int j = 0; j < 8; ++j) {
    int c = lane + 32 * j;
    v[j] = g_base[b * D + c] + temb[t * D + c];
    g_h[(size_t)row * D + c] = v[j];
    s += v[j];
  }
#pragma unroll
  for (int o2 = 16; o2; o2 >>= 1) s += __shfl_xor_sync(0xffffffffu, s, o2);
  float mu = s * (1.f / D);
  float s2 = 0.f;
#pragma unroll
  for (int j = 0; j < 8; ++j) { float dv = v[j] - mu; s2 += dv * dv; }
#pragma unroll
  for (int o2 = 16; o2; o2 >>= 1) s2 += __shfl_xor_sync(0xffffffffu, s2, o2);
  float inv = rsqrtf(s2 * (1.f / D) + 1e-5f);
#pragma unroll
  for (int j = 0; j < 8; ++j) {
    int c = lane + 32 * j;
    float r = (v[j] - mu) * inv * g[c] + be[c];
    g_xnh[(size_t)row * D + c] = __float2half_rn(r);
  }
}

// ---------------- LayerNorm (warp per row) ---------------------------------
template <bool HF>
__global__ void k_ln_t(const float* __restrict__ x, const float* __restrict__ g,
                       const float* __restrict__ be, float* __restrict__ o,
                       __half* __restrict__ oh) {
  int row  = blockIdx.x * 8 + (threadIdx.x >> 5);
  int lane = threadIdx.x & 31;
  const float* xr = x + (size_t)row * D;
  float v[8];
  float s = 0.f;
#pragma unroll
  for (int j = 0; j < 8; ++j) { v[j] = xr[lane + 32 * j]; s += v[j]; }
#pragma unroll
  for (int o2 = 16; o2; o2 >>= 1) s += __shfl_xor_sync(0xffffffffu, s, o2);
  float mu = s * (1.f / D);
  float s2 = 0.f;
#pragma unroll
  for (int j = 0; j < 8; ++j) { float dv = v[j] - mu; s2 += dv * dv; }
#pragma unroll
  for (int o2 = 16; o2; o2 >>= 1) s2 += __shfl_xor_sync(0xffffffffu, s2, o2);
  float inv = rsqrtf(s2 * (1.f / D) + 1e-5f);
#pragma unroll
  for (int j = 0; j < 8; ++j) {
    int c = lane + 32 * j;
    float r = (v[j] - mu) * inv * g[c] + be[c];
    if (HF) oh[(size_t)row * D + c] = __float2half_rn(r);
    else    o[(size_t)row * D + c] = r;
  }
}

// ---------------- SGEMM (fp32, small final GEMM only) ----------------------
template <int BM, int BN, int BK, int TM, int TN>
__global__ void __launch_bounds__((BM / TM) * (BN / TN))
sgemm_nt(const float* __restrict__ A, const float* __restrict__ Bm,
         const float* __restrict__ bias, float* __restrict__ C,
         int M, int N, int K) {
  constexpr int NT = (BM / TM) * (BN / TN);
  __shared__ float As[BK][BM];
  __shared__ float Bs[BK][BN];
  int tid = threadIdx.x;
  int bn = blockIdx.x, bm = blockIdx.y;
  const float* Ab = A  + (size_t)bm * BM * K;
  const float* Bb = Bm + (size_t)bn * BN * K;
  int tx = tid % (BN / TN), ty = tid / (BN / TN);
  float acc[TM][TN] = {};
  for (int k0 = 0; k0 < K; k0 += BK) {
    for (int i = tid * 4; i < BM * BK; i += NT * 4) {
      int r = i / BK, c = i % BK;
      float4 v = *reinterpret_cast<const float4*>(Ab + (size_t)r * K + k0 + c);
      As[c + 0][r] = v.x; As[c + 1][r] = v.y; As[c + 2][r] = v.z; As[c + 3][r] = v.w;
    }
    for (int i = tid * 4; i < BN * BK; i += NT * 4) {
      int r = i / BK, c = i % BK;
      float4 v = *reinterpret_cast<const float4*>(Bb + (size_t)r * K + k0 + c);
      Bs[c + 0][r] = v.x; Bs[c + 1][r] = v.y; Bs[c + 2][r] = v.z; Bs[c + 3][r] = v.w;
    }
    __syncthreads();
#pragma unroll
    for (int k = 0; k < BK; ++k) {
      float ra[TM], rb[TN];
#pragma unroll
      for (int i = 0; i < TM; ++i) ra[i] = As[k][ty * TM + i];
#pragma unroll
      for (int j = 0; j < TN; ++j) rb[j] = Bs[k][tx * TN + j];
#pragma unroll
      for (int i = 0; i < TM; ++i)
#pragma unroll
        for (int j = 0; j < TN; ++j) acc[i][j] = fmaf(ra[i], rb[j], acc[i][j]);
    }
    __syncthreads();
  }
#pragma unroll
  for (int i = 0; i < TM; ++i) {
    int m = bm * BM + ty * TM + i;
    float* Cr = C + (size_t)m * N + bn * BN + tx * TN;
#pragma unroll
    for (int j = 0; j < TN; ++j) Cr[j] = acc[i][j] + bias[bn * BN + tx * TN + j];
  }
}

// ---------------- k_mid: fused conv+silu, dbc, dt --------------------------
// block = 16 consecutive t rows of one batch; 256 threads.
// dynamic smem layout (floats):
//   [0, 8192)        s_xs  16x512
//   [8192, 17920)    s_xc  19x512      (dead after conv)
//   [8192, 12288)    s_w   8x512       (dbc weight chunk, reuses xc)
//   [12288, 13056)   s_dbc 16x48
constexpr int MID_TT   = 16;
constexpr int MID_SMEM = 17920 * 4;

__global__ void __launch_bounds__(256)
k_mid(const float* __restrict__ cw, const float* __restrict__ cb,
      const float* __restrict__ xpw, const float* __restrict__ dtw,
      const float* __restrict__ dtb) {
  extern __shared__ float sm[];
  float* s_xs  = sm;
  float* s_xc  = sm + 8192;
  float* s_w   = sm + 8192;
  float* s_dbc = sm + 12288;

  const int tid  = threadIdx.x;
  const int lane = tid & 31, wid = tid >> 5;
  const int blk  = blockIdx.x;
  const int b    = blk >> 6;              // L/MID_TT = 64 tiles per batch
  const int t0   = (blk & 63) * MID_TT;
  const size_t rowbase = (size_t)b * L;

  // ---- 1. load xc rows [t0-3, t0+16) --------------------------------------
  for (int i = tid; i < 19 * 128; i += 256) {
    int r = i >> 7, c4 = i & 127;
    int t = t0 - 3 + r;
    float4 v = make_float4(0.f, 0.f, 0.f, 0.f);
    if (t >= 0)
      v = *reinterpret_cast<const float4*>(g_xz + (rowbase + t) * (2 * DI) + c4 * 4);
    *reinterpret_cast<float4*>(s_xc + r * DI + c4 * 4) = v;
  }
  __syncthreads();

  // ---- 2. conv + silu -> s_xs, g_xs ----------------------------------------
  {
    const int c4 = tid & 127;             // fixed 4-channel group per thread
    const int d  = c4 * 4;
    float4 wv[KC];
#pragma unroll
    for (int k = 0; k < KC; ++k) {
      wv[k].x = cw[(d + 0) * KC + k];
      wv[k].y = cw[(d + 1) * KC + k];
      wv[k].z = cw[(d + 2) * KC + k];
      wv[k].w = cw[(d + 3) * KC + k];
    }
    float4 bv = *reinterpret_cast<const float4*>(cb + d);
#pragma unroll
    for (int i = 0; i < 8; ++i) {
      int tt = (tid >> 7) + 2 * i;
      float4 acc = bv;
#pragma unroll
      for (int k = 0; k < KC; ++k) {
        float4 x = *reinterpret_cast<const float4*>(s_xc + (tt + k) * DI + d);
        acc.x = fmaf(x.x, wv[k].x, acc.x);
        acc.y = fmaf(x.y, wv[k].y, acc.y);
        acc.z = fmaf(x.z, wv[k].z, acc.z);
        acc.w = fmaf(x.w, wv[k].w, acc.w);
      }
      float4 o;
      o.x = siluf(acc.x); o.y = siluf(acc.y);
      o.z = siluf(acc.z); o.w = siluf(acc.w);
      *reinterpret_cast<float4*>(s_xs + tt * DI + d) = o;
      *reinterpret_cast<float4*>(g_xs + (rowbase + t0 + tt) * DI + d) = o;
    }
  }
  __syncthreads();

  // ---- 3. dbc = xs @ xp_w^T (48 outputs per row) ---------------------------
  {
    const int r0 = wid * 2;               // each warp: rows r0, r0+1
    float v0[16], v1[16];
#pragma unroll
    for (int j = 0; j < 16; ++j) {
      v0[j] = s_xs[r0 * DI + lane + 32 * j];
      v1[j] = s_xs[(r0 + 1) * DI + lane + 32 * j];
    }
    for (int nc = 0; nc < 6; ++nc) {
      // load 8 weight rows into s_w (overwrites xc region)
      for (int i = tid; i < 8 * 128; i += 256) {
        int n = i >> 7, c4 = i & 127;
        *reinterpret_cast<float4*>(s_w + n * DI + c4 * 4) =
            *reinterpret_cast<const float4*>(xpw + (size_t)(nc * 8 + n) * DI + c4 * 4);
      }
      __syncthreads();
#pragma unroll
      for (int n = 0; n < 8; ++n) {
        float a0 = 0.f, a1 = 0.f;
#pragma unroll
        for (int j = 0; j < 16; ++j) {
          float w = s_w[n * DI + lane + 32 * j];
          a0 = fmaf(v0[j], w, a0);
          a1 = fmaf(v1[j], w, a1);
        }
#pragma unroll
        for (int o = 16; o; o >>= 1) {
          a0 += __shfl_xor_sync(0xffffffffu, a0, o);
          a1 += __shfl_xor_sync(0xffffffffu, a1, o);
        }
        if (lane == 0) {
          s_dbc[r0 * 48 + nc * 8 + n]       = a0;
          s_dbc[(r0 + 1) * 48 + nc * 8 + n] = a1;
        }
      }
      __syncthreads();
    }
  }

  // ---- 4. dbc -> global (B/C for scan) -------------------------------------
  for (int i = tid; i < MID_TT * 48; i += 256) {
    int tt = i / 48, n = i % 48;
    g_dbc[(rowbase + t0 + tt) * 48 + n] = s_dbc[tt * 48 + n];
  }

  // ---- 5. dt = softplus(dbc[:, :16] @ dt_w^T + dt_b) -----------------------
  {
    const int d0 = tid * 2;               // two d per thread
    float w0[16], w1[16];
#pragma unroll
    for (int k = 0; k < DTR; ++k) {
      w0[k] = dtw[(d0 + 0) * DTR + k];
      w1[k] = dtw[(d0 + 1) * DTR + k];
    }
    float b0 = dtb[d0], b1 = dtb[d0 + 1];
#pragma unroll 4
    for (int tt = 0; tt < MID_TT; ++tt) {
      float a0 = b0, a1 = b1;
#pragma unroll
      for (int k = 0; k < DTR; ++k) {
        float r = s_dbc[tt * 48 + k];
        a0 = fmaf(r, w0[k], a0);
        a1 = fmaf(r, w1[k], a1);
      }
      a0 = (a0 > 20.f) ? a0 : log1pf(__expf(a0));
      a1 = (a1 > 20.f) ? a1 : log1pf(__expf(a1));
      *reinterpret_cast<float2*>(g_dt + (rowbase + t0 + tt) * DI + d0) =
          make_float2(a0, a1);
    }
  }
}

// ---------------- selective scan: cp.async tile pipeline --------------------
// 256 blocks (b, 32-d chunk), 512 threads = 32 d x 16 s.
constexpr int SCT = 8;
constexpr int SCS = 3;
__global__ void __launch_bounds__(512) k_scan(const float* __restrict__ A_log,
                                              const float* __restrict__ Dp) {
  __shared__ __align__(16) float sdt[SCS][SCT][32];
  __shared__ __align__(16) float sxs[SCS][SCT][32];
  __shared__ __align__(16) float szg[SCS][SCT][32];
  __shared__ __align__(16) float sB [SCS][SCT][16];
  __shared__ __align__(16) float sC [SCS][SCT][16];

  const int tid = threadIdx.x;
  const int b  = blockIdx.x >> 4;
  const int dc = blockIdx.x & 15;
  const int s  = tid & 15;
  const int dl = tid >> 4;                // 0..31
  const int d  = dc * 32 + dl;
  const float a  = -expf(A_log[d * DS + s]);
  const float dp = Dp[d];
  const size_t rowbase = (size_t)b * L;

  const float* gdt = g_dt  + rowbase * DI + dc * 32;
  const float* gxs = g_xs  + rowbase * DI + dc * 32;
  const float* gzg = g_xz  + rowbase * (2 * DI) + DI + dc * 32;
  const float* gB  = g_dbc + rowbase * 48 + 16;
  const float* gC  = g_dbc + rowbase * 48 + 32;

  auto issue = [&](int tile, int st) {
    int t0 = tile * SCT;
    if (tid < 64) {                        // dt: 8 rows x 8 f4
      int r = tid >> 3, c = tid & 7;
      cp16(smem_u32(&sdt[st][r][c * 4]), gdt + (size_t)(t0 + r) * DI + c * 4);
    } else if (tid < 128) {
      int q = tid - 64, r = q >> 3, c = q & 7;
      cp16(smem_u32(&sxs[st][r][c * 4]), gxs + (size_t)(t0 + r) * DI + c * 4);
    } else if (tid < 192) {
      int q = tid - 128, r = q >> 3, c = q & 7;
      cp16(smem_u32(&szg[st][r][c * 4]), gzg + (size_t)(t0 + r) * (2 * DI) + c * 4);
    } else if (tid < 224) {
      int q = tid - 192, r = q >> 2, c = q & 3;
      cp16(smem_u32(&sB[st][r][c * 4]), gB + (size_t)(t0 + r) * 48 + c * 4);
    } else if (tid < 256) {
      int q = tid - 224, r = q >> 2, c = q & 3;
      cp16(smem_u32(&sC[st][r][c * 4]), gC + (size_t)(t0 + r) * 48 + c * 4);
    }
    cp_commit();
  };

  float h = 0.f;
  __half* pyh = g_yh + rowbase * DI + d;

  constexpr int NT = L / SCT;
  issue(0, 0);
  issue(1, 1);
  for (int i = 0; i < NT; ++i) {
    cp_wait<1>();
    __syncthreads();
    if (i + 2 < NT) issue(i + 2, (i + 2) % SCS);
    int st = i % SCS;
#pragma unroll
    for (int t = 0; t < SCT; ++t) {
      float dtv = sdt[st][t][dl];
      float xv  = sxs[st][t][dl];
      float Bv  = sB [st][t][s];
      float Cv  = sC [st][t][s];
      float e = __expf(dtv * a);
      h = fmaf(e, h, dtv * xv * Bv);
      float val = h * Cv;
#pragma unroll
      for (int o = 8; o; o >>= 1)
        val += __shfl_xor_sync(0xffffffffu, val, o, 16);
      if (s == 0) {
        float zg = szg[st][t][dl];
        float vy = (val + xv * dp) * siluf(zg);
        pyh[(size_t)(i * SCT + t) * DI] = __float2half_rn(vy);
      }
    }
    __syncthreads();
  }
}

// ---------------- launch ----------------------------------------------------
extern "C" void kernel_launch(void* const* d_in, const int* in_sizes, int n_in,
                              void* d_out, int out_size) {
  const float* z      = (const float*)d_in[0];
  const float* lg     = (const float*)d_in[1];
  const float* lb     = (const float*)d_in[2];
  const float* lw     = (const float*)d_in[3];
  const float* lbias  = (const float*)d_in[4];
  const float* temb   = (const float*)d_in[5];
  const float* ln_g   = (const float*)d_in[6];
  const float* ln_b   = (const float*)d_in[7];
  const float* in_w   = (const float*)d_in[8];
  const float* in_b   = (const float*)d_in[9];
  const float* conv_w = (const float*)d_in[10];
  const float* conv_b = (const float*)d_in[11];
  const float* xp_w   = (const float*)d_in[12];
  const float* dt_w   = (const float*)d_in[13];
  const float* dt_b   = (const float*)d_in[14];
  const float* A_log  = (const float*)d_in[15];
  const float* Dp     = (const float*)d_in[16];
  const float* out_w  = (const float*)d_in[17];
  const float* out_b  = (const float*)d_in[18];
  const float* on_g   = (const float*)d_in[19];
  const float* on_b   = (const float*)d_in[20];
  const float* op_w   = (const float*)d_in[21];
  const float* op_b   = (const float*)d_in[22];
  float* out = (float*)d_out;

  float *p_h, *p_xn;
  __half *p_xnh, *p_yh, *p_wi, *p_wo;
  cudaGetSymbolAddress((void**)&p_h,   g_h);
  cudaGetSymbolAddress((void**)&p_xn,  g_xn);
  cudaGetSymbolAddress((void**)&p_xnh, g_xnh);
  cudaGetSymbolAddress((void**)&p_yh,  g_yh);
  cudaGetSymbolAddress((void**)&p_wi,  g_wi);
  cudaGetSymbolAddress((void**)&p_wo,  g_wo);
  float* p_xz;
  cudaGetSymbolAddress((void**)&p_xz,  g_xz);

  cudaFuncSetAttribute(hmma_gemm<false>,
                       cudaFuncAttributeMaxDynamicSharedMemorySize, SMEM_H);
  cudaFuncSetAttribute(hmma_gemm<true>,
                       cudaFuncAttributeMaxDynamicSharedMemorySize, SMEM_H);
  cudaFuncSetAttribute(k_mid,
                       cudaFuncAttributeMaxDynamicSharedMemorySize, MID_SMEM);

  const int NW = NL * 2 * DI * D + NL * D * DI;
  k_prep<<<B + (NW + 255) / 256, 256>>>(in_w, out_w, z, lg, lb, lw, lbias); // 1

  for (int i = 0; i < NL; ++i) {
    if (i == 0)
      k_ln0<<<NR / 8, 256>>>(temb, ln_g, ln_b);                             // 2
    else
      k_ln_t<true><<<NR / 8, 256>>>(p_h, ln_g + i * D, ln_b + i * D,
                                    nullptr, p_xnh);
    hmma_gemm<false><<<dim3(8, NR / 128), 256, SMEM_H>>>(                   // 3
        p_xnh, p_wi + (size_t)i * 2 * DI * D, in_b + i * 2 * DI, p_xz,
        2 * DI, D);
    k_mid<<<NR / MID_TT, 256, MID_SMEM>>>(                                  // 4
        conv_w + i * DI * KC, conv_b + i * DI, xp_w + (size_t)i * 48 * DI,
        dt_w + i * DI * DTR, dt_b + i * DI);
    k_scan<<<B * 16, 512>>>(A_log + i * DI * DS, Dp + i * DI);
    hmma_gemm<true><<<dim3(2, NR / 128), 256, SMEM_H>>>(
        p_yh, p_wo + (size_t)i * D * DI, out_b + i * D, p_h, D, DI);
  }

  k_ln_t<false><<<NR / 8, 256>>>(p_h, on_g, on_b, p_xn, nullptr);
  sgemm_nt<128, 64, 8, 8, 4>
      <<<dim3(1, NR / 128), 256>>>(p_xn, op_w, op_b, out, NR, OUTD, D);
}

// round 7
// speedup vs baseline: 4.8046x; 1.6154x over previous
#include <cuda_runtime.h>
#include <cuda_fp16.h>
#include <math.h>
#include <stdint.h>

namespace {
constexpr int B  = 16,  LAT = 256, D  = 256, DI = 512, DS = 16, DTR = 16;
constexpr int L  = 1024, KC = 4,  OUTD = 64, NL = 4;
constexpr int NR = B * L;
}

// ---------------- scratch ---------------------------------------------------
__device__ float g_h   [NR * D];
__device__ float g_xz  [NR * 2 * DI];
__device__ float g_xs  [NR * DI];
__device__ float g_zs  [NR * DI];
__device__ float g_dbc [NR * 64];        // padded stride 64: [0:16)=dt-in, [16:32)=B, [32:48)=C
__device__ float g_base[B * D];
__device__ float g_zb  [64];             // zero bias (zero-init)
__device__ __half g_xnh[NR * D], g_xnl[NR * D];
__device__ __half g_xsh[NR * DI], g_xsl[NR * DI];
__device__ __half g_yh [NR * DI];
__device__ __half g_wi  [NL * 2 * DI * D];
__device__ __half g_wo  [NL * D * DI];
__device__ __half g_xpwh[NL * 64 * DI];  // padded 48->64 rows
__device__ __half g_opwh[OUTD * D];

// ---------------- PTX helpers ----------------------------------------------
__device__ __forceinline__ uint32_t smem_u32(const void* p) {
  uint32_t a;
  asm("{ .reg .u64 t; cvta.to.shared.u64 t, %1; cvt.u32.u64 %0, t; }"
      : "=r"(a) : "l"(p));
  return a;
}
__device__ __forceinline__ void cp16(uint32_t dst, const void* src) {
  asm volatile("cp.async.cg.shared.global [%0], [%1], 16;" ::"r"(dst),
               "l"(src));
}
__device__ __forceinline__ void cp_commit() {
  asm volatile("cp.async.commit_group;" ::: "memory");
}
template <int N>
__device__ __forceinline__ void cp_wait() {
  asm volatile("cp.async.wait_group %0;" ::"n"(N) : "memory");
}
__device__ __forceinline__ void ldsm4(uint32_t (&r)[4], uint32_t addr) {
  asm volatile(
      "ldmatrix.sync.aligned.m8n8.x4.shared.b16 {%0,%1,%2,%3}, [%4];"
      : "=r"(r[0]), "=r"(r[1]), "=r"(r[2]), "=r"(r[3])
      : "r"(addr));
}
__device__ __forceinline__ void mma16816(float (&d)[4], const uint32_t (&a)[4],
                                         uint32_t b0, uint32_t b1) {
  asm volatile(
      "mma.sync.aligned.m16n8k16.row.col.f32.f16.f16.f32 "
      "{%0,%1,%2,%3}, {%4,%5,%6,%7}, {%8,%9}, {%0,%1,%2,%3};"
      : "+f"(d[0]), "+f"(d[1]), "+f"(d[2]), "+f"(d[3])
      : "r"(a[0]), "r"(a[1]), "r"(a[2]), "r"(a[3]), "r"(b0), "r"(b1));
}

// ---------------- math helpers ---------------------------------------------
__device__ __forceinline__ float geluf(float x) {
  return 0.5f * x * (1.f + erff(x * 0.70710678118654752f));
}
__device__ __forceinline__ float siluf(float x) {
  return __fdividef(x, 1.f + __expf(-x));
}
__device__ __forceinline__ float blk_sum_256(float v, float* red) {
  __syncthreads();
  int lane = threadIdx.x & 31, w = threadIdx.x >> 5;
#pragma unroll
  for (int o = 16; o; o >>= 1) v += __shfl_xor_sync(0xffffffffu, v, o);
  if (lane == 0) red[w] = v;
  __syncthreads();
  if (threadIdx.x < 32) {
    float t = (threadIdx.x < 8) ? red[threadIdx.x] : 0.f;
#pragma unroll
    for (int o = 4; o; o >>= 1) t += __shfl_xor_sync(0xffffffffu, t, o);
    if (threadIdx.x == 0) red[0] = t;
  }
  __syncthreads();
  return red[0];
}

// ---------------- HMMA GEMM 128x128: C = A@B^T + bias [+C] -----------------
constexpr int LDSE   = 40;
constexpr int ARR_B  = 128 * LDSE * 2;   // 10240
constexpr int STG_B  = 2 * ARR_B;        // 20480
constexpr int SMEM_H = 4 * STG_B;        // 81920

template <bool ACCUM>
__global__ void __launch_bounds__(256, 2)
hmma_gemm(const __half* __restrict__ Ah, const __half* __restrict__ Bw,
          const float* __restrict__ bias, float* __restrict__ C,
          int N, int K) {
  extern __shared__ char smem[];
  const uint32_t sb = smem_u32(smem);
  const int tid = threadIdx.x, lane = tid & 31, wid = tid >> 5;
  const int wm = wid >> 1, wn = wid & 1;
  const int m0 = blockIdx.y * 128, n0 = blockIdx.x * 128;

  float acc[2][8][4] = {};
  const int nchunk = K >> 5;

  auto issue = [&](int s, int k0) {
    uint32_t st = sb + s * STG_B;
#pragma unroll
    for (int i = 0; i < 2; ++i) {
      int seg = tid + i * 256;
      int r = seg >> 2, c4 = seg & 3;
      uint32_t so = r * (LDSE * 2) + c4 * 16;
      cp16(st + 0 * ARR_B + so, Ah + (size_t)(m0 + r) * K + k0 + c4 * 8);
      cp16(st + 1 * ARR_B + so, Bw + (size_t)(n0 + r) * K + k0 + c4 * 8);
    }
    cp_commit();
  };

  auto compute = [&](int s) {
    uint32_t st = sb + s * STG_B;
#pragma unroll
    for (int ks = 0; ks < 32; ks += 16) {
      uint32_t aH[2][4];
#pragma unroll
      for (int mi = 0; mi < 2; ++mi) {
        uint32_t ro = wm * 32 + mi * 16 + (lane & 15);
        uint32_t co = ks + ((lane >> 4) & 1) * 8;
        ldsm4(aH[mi], st + (ro * LDSE + co) * 2);
      }
#pragma unroll
      for (int p = 0; p < 4; ++p) {
        uint32_t bh[4];
        uint32_t nr = wn * 64 + p * 16 + (lane & 7) + ((lane >> 4) & 1) * 8;
        uint32_t kc = ks + ((lane >> 3) & 1) * 8;
        ldsm4(bh, st + 1 * ARR_B + (nr * LDSE + kc) * 2);
#pragma unroll
        for (int mi = 0; mi < 2; ++mi)
#pragma unroll
          for (int q = 0; q < 2; ++q)
            mma16816(acc[mi][p * 2 + q], aH[mi], bh[q * 2], bh[q * 2 + 1]);
      }
    }
  };

  issue(0, 0); issue(1, 32); issue(2, 64);
  for (int c = 0; c < nchunk; ++c) {
    cp_wait<2>();
    __syncthreads();
    if (c + 3 < nchunk) issue((c + 3) & 3, (c + 3) * 32);
    else cp_commit();
    compute(c & 3);
  }

  const int mb = m0 + wm * 32 + (lane >> 2);
  const int nb = n0 + wn * 64 + (lane & 3) * 2;
#pragma unroll
  for (int mi = 0; mi < 2; ++mi) {
#pragma unroll
    for (int ni = 0; ni < 8; ++ni) {
      int c = nb + ni * 8;
      float b0 = bias[c], b1 = bias[c + 1];
      float* p0 = C + (size_t)(mb + mi * 16) * N + c;
      float* p1 = C + (size_t)(mb + mi * 16 + 8) * N + c;
      float2 v0 = make_float2(acc[mi][ni][0] + b0, acc[mi][ni][1] + b1);
      float2 v1 = make_float2(acc[mi][ni][2] + b0, acc[mi][ni][3] + b1);
      if (ACCUM) {
        float2 o0 = *reinterpret_cast<float2*>(p0);
        float2 o1 = *reinterpret_cast<float2*>(p1);
        v0.x += o0.x; v0.y += o0.y; v1.x += o1.x; v1.y += o1.y;
      }
      *reinterpret_cast<float2*>(p0) = v0;
      *reinterpret_cast<float2*>(p1) = v1;
    }
  }
}

// ---------------- HMMA GEMM 128x64, split-fp16 A (hi+lo): C = (Ah+Al)@B^T --
constexpr int DA_B  = 128 * LDSE * 2;    // 10240
constexpr int DB_B  = 64 * LDSE * 2;     // 5120
constexpr int DSTG  = 2 * DA_B + DB_B;   // 25600
constexpr int SMEM_D = 4 * DSTG;         // 102400

__global__ void __launch_bounds__(256, 1)
hmma_nk64(const __half* __restrict__ Ah, const __half* __restrict__ Al,
          const __half* __restrict__ Bw, const float* __restrict__ bias,
          float* __restrict__ C, int K) {
  extern __shared__ char smem[];
  const uint32_t sb = smem_u32(smem);
  const int tid = threadIdx.x, lane = tid & 31, wid = tid >> 5;
  const int wm = wid >> 1, wn = wid & 1;
  const int m0 = blockIdx.x * 128;

  float acc[2][4][4] = {};
  const int nchunk = K >> 5;

  auto issue = [&](int s, int k0) {
    uint32_t st = sb + s * DSTG;
#pragma unroll
    for (int i = 0; i < 2; ++i) {
      int seg = tid + i * 256;
      int r = seg >> 2, c4 = seg & 3;
      uint32_t so = r * (LDSE * 2) + c4 * 16;
      cp16(st + 0 * DA_B + so, Ah + (size_t)(m0 + r) * K + k0 + c4 * 8);
      cp16(st + 1 * DA_B + so, Al + (size_t)(m0 + r) * K + k0 + c4 * 8);
    }
    {
      int r = tid >> 2, c4 = tid & 3;  // 64 rows x 4
      cp16(st + 2 * DA_B + r * (LDSE * 2) + c4 * 16,
           Bw + (size_t)r * K + k0 + c4 * 8);
    }
    cp_commit();
  };

  auto compute = [&](int s) {
    uint32_t st = sb + s * DSTG;
#pragma unroll
    for (int ks = 0; ks < 32; ks += 16) {
      uint32_t aH[2][4], aL[2][4];
#pragma unroll
      for (int mi = 0; mi < 2; ++mi) {
        uint32_t ro = wm * 32 + mi * 16 + (lane & 15);
        uint32_t co = ks + ((lane >> 4) & 1) * 8;
        ldsm4(aH[mi], st + (ro * LDSE + co) * 2);
        ldsm4(aL[mi], st + DA_B + (ro * LDSE + co) * 2);
      }
#pragma unroll
      for (int p = 0; p < 2; ++p) {
        uint32_t bh[4];
        uint32_t nr = wn * 32 + p * 16 + (lane & 7) + ((lane >> 4) & 1) * 8;
        uint32_t kc = ks + ((lane >> 3) & 1) * 8;
        ldsm4(bh, st + 2 * DA_B + (nr * LDSE + kc) * 2);
#pragma unroll
        for (int mi = 0; mi < 2; ++mi)
#pragma unroll
          for (int q = 0; q < 2; ++q) {
            mma16816(acc[mi][p * 2 + q], aH[mi], bh[q * 2], bh[q * 2 + 1]);
            mma16816(acc[mi][p * 2 + q], aL[mi], bh[q * 2], bh[q * 2 + 1]);
          }
      }
    }
  };

  issue(0, 0); issue(1, 32); issue(2, 64);
  for (int c = 0; c < nchunk; ++c) {
    cp_wait<2>();
    __syncthreads();
    if (c + 3 < nchunk) issue((c + 3) & 3, (c + 3) * 32);
    else cp_commit();
    compute(c & 3);
  }

  const int mb = m0 + wm * 32 + (lane >> 2);
  const int nb = wn * 32 + (lane & 3) * 2;
#pragma unroll
  for (int mi = 0; mi < 2; ++mi) {
#pragma unroll
    for (int ni = 0; ni < 4; ++ni) {
      int c = nb + ni * 8;
      float b0 = bias[c], b1 = bias[c + 1];
      float* p0 = C + (size_t)(mb + mi * 16) * 64 + c;
      float* p1 = C + (size_t)(mb + mi * 16 + 8) * 64 + c;
      *reinterpret_cast<float2*>(p0) =
          make_float2(acc[mi][ni][0] + b0, acc[mi][ni][1] + b1);
      *reinterpret_cast<float2*>(p1) =
          make_float2(acc[mi][ni][2] + b0, acc[mi][ni][3] + b1);
    }
  }
}

// ---------------- k_prep: weight conversions + base ------------------------
__global__ void k_prep(const float* __restrict__ in_w,
                       const float* __restrict__ out_w,
                       const float* __restrict__ xp_w,
                       const float* __restrict__ op_w,
                       const float* __restrict__ z, const float* __restrict__ lg,
                       const float* __restrict__ lb, const float* __restrict__ lw,
                       const float* __restrict__ lbias) {
  __shared__ float xn[LAT];
  __shared__ float red[32];
  const int NIW = NL * 2 * DI * D, NOW = NL * D * DI;
  const int NXP = NL * 64 * DI, NOP = OUTD * D;
  if (blockIdx.x < B) {
    int b = blockIdx.x, tid = threadIdx.x;
    float v  = z[b * LAT + tid];
    float mu = blk_sum_256(v, red) * (1.f / LAT);
    float dv = v - mu;
    float var = blk_sum_256(dv * dv, red) * (1.f / LAT);
    float inv = rsqrtf(var + 1e-5f);
    xn[tid] = dv * inv * lg[tid] + lb[tid];
    __syncthreads();
    float acc = lbias[tid];
    const float* wr = lw + tid * LAT;
#pragma unroll 8
    for (int k = 0; k < LAT; ++k) acc = fmaf(xn[k], wr[k], acc);
    g_base[b * D + tid] = geluf(acc);
  } else {
    int i = (blockIdx.x - B) * 256 + threadIdx.x;
    if (i < NIW) {
      g_wi[i] = __float2half_rn(in_w[i]);
    } else if (i < NIW + NOW) {
      g_wo[i - NIW] = __float2half_rn(out_w[i - NIW]);
    } else if (i < NIW + NOW + NXP) {
      int j = i - NIW - NOW;
      int l = j >> 15, r = (j >> 9) & 63, c = j & 511;
      g_xpwh[j] = (r < 48)
          ? __float2half_rn(xp_w[(size_t)l * 48 * DI + r * DI + c])
          : __float2half_rn(0.f);
    } else if (i < NIW + NOW + NXP + NOP) {
      int j = i - NIW - NOW - NXP;
      g_opwh[j] = __float2half_rn(op_w[j]);
    }
  }
}

// ---------------- layer-0 LN: h = base + temb -> LN -> fp16 ----------------
__global__ void k_ln0(const float* __restrict__ temb, const float* __restrict__ g,
                      const float* __restrict__ be) {
  int row  = blockIdx.x * 8 + (threadIdx.x >> 5);
  int lane = threadIdx.x & 31;
  int b = row >> 10, t = row & (L - 1);
  float v[8];
  float s = 0.f;
#pragma unroll
  for (int j = 0; j < 8; ++j) {
    int c = lane + 32 * j;
    v[j] = g_base[b * D + c] + temb[t * D + c];
    g_h[(size_t)row * D + c] = v[j];
    s += v[j];
  }
#pragma unroll
  for (int o2 = 16; o2; o2 >>= 1) s += __shfl_xor_sync(0xffffffffu, s, o2);
  float mu = s * (1.f / D);
  float s2 = 0.f;
#pragma unroll
  for (int j = 0; j < 8; ++j) { float dv = v[j] - mu; s2 += dv * dv; }
#pragma unroll
  for (int o2 = 16; o2; o2 >>= 1) s2 += __shfl_xor_sync(0xffffffffu, s2, o2);
  float inv = rsqrtf(s2 * (1.f / D) + 1e-5f);
#pragma unroll
  for (int j = 0; j < 8; ++j) {
    int c = lane + 32 * j;
    float r = (v[j] - mu) * inv * g[c] + be[c];
    g_xnh[(size_t)row * D + c] = __float2half_rn(r);
  }
}

// ---------------- LayerNorm; MODE 1 = fp16 hi; MODE 2 = fp16 hi+lo ---------
template <int MODE>
__global__ void k_ln_t(const float* __restrict__ x, const float* __restrict__ g,
                       const float* __restrict__ be,
                       __half* __restrict__ oh, __half* __restrict__ ol) {
  int row  = blockIdx.x * 8 + (threadIdx.x >> 5);
  int lane = threadIdx.x & 31;
  const float* xr = x + (size_t)row * D;
  float v[8];
  float s = 0.f;
#pragma unroll
  for (int j = 0; j < 8; ++j) { v[j] = xr[lane + 32 * j]; s += v[j]; }
#pragma unroll
  for (int o2 = 16; o2; o2 >>= 1) s += __shfl_xor_sync(0xffffffffu, s, o2);
  float mu = s * (1.f / D);
  float s2 = 0.f;
#pragma unroll
  for (int j = 0; j < 8; ++j) { float dv = v[j] - mu; s2 += dv * dv; }
#pragma unroll
  for (int o2 = 16; o2; o2 >>= 1) s2 += __shfl_xor_sync(0xffffffffu, s2, o2);
  float inv = rsqrtf(s2 * (1.f / D) + 1e-5f);
#pragma unroll
  for (int j = 0; j < 8; ++j) {
    int c = lane + 32 * j;
    float r = (v[j] - mu) * inv * g[c] + be[c];
    __half hi = __float2half_rn(r);
    oh[(size_t)row * D + c] = hi;
    if (MODE == 2)
      ol[(size_t)row * D + c] = __float2half_rn(r - __half2float(hi));
  }
}

// ---------------- k_conv: conv+silu (xs f32 + fp16 hi/lo) and silu(zg) -----
// thread = (b, 4-row group, 4-channel group)
__global__ void __launch_bounds__(256) k_conv(const float* __restrict__ cw,
                                              const float* __restrict__ cb) {
  int idx = blockIdx.x * 256 + threadIdx.x;   // NR/4 * 128
  int d4 = idx & 127;
  int tb = (idx >> 7) & 255;
  int b  = idx >> 15;
  int d  = d4 * 4;
  int t0 = tb * 4;
  const float* xz = g_xz + (size_t)b * L * (2 * DI);

  float4 w0 = *reinterpret_cast<const float4*>(cw + (d + 0) * KC);
  float4 w1 = *reinterpret_cast<const float4*>(cw + (d + 1) * KC);
  float4 w2 = *reinterpret_cast<const float4*>(cw + (d + 2) * KC);
  float4 w3 = *reinterpret_cast<const float4*>(cw + (d + 3) * KC);
  float4 bv = *reinterpret_cast<const float4*>(cb + d);

  float4 x[7];
#pragma unroll
  for (int j = 0; j < 7; ++j) {
    int t = t0 - 3 + j;
    x[j] = (t >= 0)
        ? *reinterpret_cast<const float4*>(xz + (size_t)t * (2 * DI) + d)
        : make_float4(0.f, 0.f, 0.f, 0.f);
  }
#pragma unroll
  for (int r = 0; r < 4; ++r) {
    float4 a = bv;
    a.x += x[r].x * w0.x + x[r + 1].x * w0.y + x[r + 2].x * w0.z + x[r + 3].x * w0.w;
    a.y += x[r].y * w1.x + x[r + 1].y * w1.y + x[r + 2].y * w1.z + x[r + 3].y * w1.w;
    a.z += x[r].z * w2.x + x[r + 1].z * w2.y + x[r + 2].z * w2.z + x[r + 3].z * w2.w;
    a.w += x[r].w * w3.x + x[r + 1].w * w3.y + x[r + 2].w * w3.z + x[r + 3].w * w3.w;
    float4 o;
    o.x = siluf(a.x); o.y = siluf(a.y); o.z = siluf(a.z); o.w = siluf(a.w);
    size_t off = ((size_t)b * L + t0 + r) * DI + d;
    *reinterpret_cast<float4*>(g_xs + off) = o;
    // split fp16
    __half hx = __float2half_rn(o.x), hy = __float2half_rn(o.y);
    __half hz = __float2half_rn(o.z), hw = __float2half_rn(o.w);
    *reinterpret_cast<__half2*>(g_xsh + off)     = __halves2half2(hx, hy);
    *reinterpret_cast<__half2*>(g_xsh + off + 2) = __halves2half2(hz, hw);
    *reinterpret_cast<__half2*>(g_xsl + off) = __halves2half2(
        __float2half_rn(o.x - __half2float(hx)),
        __float2half_rn(o.y - __half2float(hy)));
    *reinterpret_cast<__half2*>(g_xsl + off + 2) = __halves2half2(
        __float2half_rn(o.z - __half2float(hz)),
        __float2half_rn(o.w - __half2float(hw)));
    // silu(zg)
    float4 zg = *reinterpret_cast<const float4*>(
        xz + (size_t)(t0 + r) * (2 * DI) + DI + d);
    float4 zo;
    zo.x = siluf(zg.x); zo.y = siluf(zg.y); zo.z = siluf(zg.z); zo.w = siluf(zg.w);
    *reinterpret_cast<float4*>(g_zs + off) = zo;
  }
}

// ---------------- selective scan with in-scan dt ---------------------------
// 128 blocks (16 b x 8 chunks of 64 d), 256 threads = 64 d x 4 s-lanes.
constexpr int SCT = 8;
__global__ void __launch_bounds__(256) k_scan(const float* __restrict__ A_log,
                                              const float* __restrict__ Dp,
                                              const float* __restrict__ dtw,
                                              const float* __restrict__ dtb) {
  __shared__ __align__(16) float sxs[4][SCT][64];
  __shared__ __align__(16) float szs[4][SCT][64];
  __shared__ __align__(16) float sdb[4][SCT][64];

  const int tid = threadIdx.x;
  const int b  = blockIdx.x >> 3;
  const int dc = blockIdx.x & 7;
  const int ls = tid & 3;
  const int dl = tid >> 2;
  const int d  = dc * 64 + dl;

  float4 alv = *reinterpret_cast<const float4*>(A_log + d * DS + ls * 4);
  const float a0 = -__expf(alv.x), a1 = -__expf(alv.y);
  const float a2 = -__expf(alv.z), a3 = -__expf(alv.w);
  const float4 wdt = *reinterpret_cast<const float4*>(dtw + d * DTR + ls * 4);
  const float dp = Dp[d], bdt = dtb[d];
  const size_t rowbase = (size_t)b * L;

  const float* gxs = g_xs  + rowbase * DI + dc * 64;
  const float* gzs = g_zs  + rowbase * DI + dc * 64;
  const float* gdb = g_dbc + rowbase * 64;
  __half* py = g_yh + rowbase * DI + d;

  auto issue = [&](int tile) {
    int st = tile & 3, t0 = tile * SCT;
    for (int i = tid; i < 384; i += 256) {
      int r = (i >> 4) & 7, c = i & 15;
      if (i < 128)
        cp16(smem_u32(&sxs[st][r][c * 4]), gxs + (size_t)(t0 + r) * DI + c * 4);
      else if (i < 256)
        cp16(smem_u32(&szs[st][r][c * 4]), gzs + (size_t)(t0 + r) * DI + c * 4);
      else
        cp16(smem_u32(&sdb[st][r][c * 4]), gdb + (size_t)(t0 + r) * 64 + c * 4);
    }
    cp_commit();
  };

  float h0 = 0.f, h1 = 0.f, h2 = 0.f, h3 = 0.f;
  constexpr int NT = L / SCT;  // 128
  issue(0); issue(1); issue(2);
  for (int i = 0; i < NT; ++i) {
    cp_wait<2>();
    __syncthreads();
    if (i + 3 < NT) issue(i + 3);
    else cp_commit();
    const int st = i & 3;

    // dt for all 8 steps (off the serial chain)
    float ddt[SCT];
#pragma unroll
    for (int t = 0; t < SCT; ++t) {
      float4 dv = *reinterpret_cast<float4*>(&sdb[st][t][ls * 4]);
      float p = dv.x * wdt.x + dv.y * wdt.y + dv.z * wdt.z + dv.w * wdt.w;
      p += __shfl_xor_sync(0xffffffffu, p, 1, 4);
      p += __shfl_xor_sync(0xffffffffu, p, 2, 4);
      p += bdt;
      ddt[t] = (p > 20.f) ? p : __logf(1.f + __expf(p));
    }
#pragma unroll
    for (int t = 0; t < SCT; ++t) {
      float xv = sxs[st][t][dl];
      float4 Bv = *reinterpret_cast<float4*>(&sdb[st][t][16 + ls * 4]);
      float4 Cv = *reinterpret_cast<float4*>(&sdb[st][t][32 + ls * 4]);
      float dtx = ddt[t] * xv;
      h0 = fmaf(__expf(ddt[t] * a0), h0, dtx * Bv.x);
      h1 = fmaf(__expf(ddt[t] * a1), h1, dtx * Bv.y);
      h2 = fmaf(__expf(ddt[t] * a2), h2, dtx * Bv.z);
      h3 = fmaf(__expf(ddt[t] * a3), h3, dtx * Bv.w);
      float val = h0 * Cv.x;
      val = fmaf(h1, Cv.y, val);
      val = fmaf(h2, Cv.z, val);
      val = fmaf(h3, Cv.w, val);
      val += __shfl_xor_sync(0xffffffffu, val, 1, 4);
      val += __shfl_xor_sync(0xffffffffu, val, 2, 4);
      if (ls == 0) {
        float zs = szs[st][t][dl];
        py[(size_t)(i * SCT + t) * DI] =
            __float2half_rn((val + xv * dp) * zs);
      }
    }
  }
}

// ---------------- launch ----------------------------------------------------
extern "C" void kernel_launch(void* const* d_in, const int* in_sizes, int n_in,
                              void* d_out, int out_size) {
  const float* z      = (const float*)d_in[0];
  const float* lg     = (const float*)d_in[1];
  const float* lb     = (const float*)d_in[2];
  const float* lw     = (const float*)d_in[3];
  const float* lbias  = (const float*)d_in[4];
  const float* temb   = (const float*)d_in[5];
  const float* ln_g   = (const float*)d_in[6];
  const float* ln_b   = (const float*)d_in[7];
  const float* in_w   = (const float*)d_in[8];
  const float* in_b   = (const float*)d_in[9];
  const float* conv_w = (const float*)d_in[10];
  const float* conv_b = (const float*)d_in[11];
  const float* xp_w   = (const float*)d_in[12];
  const float* dt_w   = (const float*)d_in[13];
  const float* dt_b   = (const float*)d_in[14];
  const float* A_log  = (const float*)d_in[15];
  const float* Dp     = (const float*)d_in[16];
  const float* out_w  = (const float*)d_in[17];
  const float* out_b  = (const float*)d_in[18];
  const float* on_g   = (const float*)d_in[19];
  const float* on_b   = (const float*)d_in[20];
  const float* op_w   = (const float*)d_in[21];
  const float* op_b   = (const float*)d_in[22];
  float* out = (float*)d_out;

  float *p_h, *p_xz, *p_dbc, *p_zb;
  __half *p_xnh, *p_xnl, *p_yh, *p_wi, *p_wo, *p_xpwh, *p_opwh, *p_xsh, *p_xsl;
  cudaGetSymbolAddress((void**)&p_h,    g_h);
  cudaGetSymbolAddress((void**)&p_xz,   g_xz);
  cudaGetSymbolAddress((void**)&p_dbc,  g_dbc);
  cudaGetSymbolAddress((void**)&p_zb,   g_zb);
  cudaGetSymbolAddress((void**)&p_xnh,  g_xnh);
  cudaGetSymbolAddress((void**)&p_xnl,  g_xnl);
  cudaGetSymbolAddress((void**)&p_yh,   g_yh);
  cudaGetSymbolAddress((void**)&p_wi,   g_wi);
  cudaGetSymbolAddress((void**)&p_wo,   g_wo);
  cudaGetSymbolAddress((void**)&p_xpwh, g_xpwh);
  cudaGetSymbolAddress((void**)&p_opwh, g_opwh);
  cudaGetSymbolAddress((void**)&p_xsh,  g_xsh);
  cudaGetSymbolAddress((void**)&p_xsl,  g_xsl);

  cudaFuncSetAttribute(hmma_gemm<false>,
                       cudaFuncAttributeMaxDynamicSharedMemorySize, SMEM_H);
  cudaFuncSetAttribute(hmma_gemm<true>,
                       cudaFuncAttributeMaxDynamicSharedMemorySize, SMEM_H);
  cudaFuncSetAttribute(hmma_nk64,
                       cudaFuncAttributeMaxDynamicSharedMemorySize, SMEM_D);

  const int NWALL = NL * 2 * DI * D + NL * D * DI + NL * 64 * DI + OUTD * D;
  k_prep<<<B + (NWALL + 255) / 256, 256>>>(in_w, out_w, xp_w, op_w,
                                           z, lg, lb, lw, lbias);

  for (int i = 0; i < NL; ++i) {
    if (i == 0)
      k_ln0<<<NR / 8, 256>>>(temb, ln_g, ln_b);
    else
      k_ln_t<1><<<NR / 8, 256>>>(p_h, ln_g + i * D, ln_b + i * D,
                                 p_xnh, nullptr);
    hmma_gemm<false><<<dim3(8, NR / 128), 256, SMEM_H>>>(
        p_xnh, p_wi + (size_t)i * 2 * DI * D, in_b + i * 2 * DI, p_xz,
        2 * DI, D);
    k_conv<<<NR / 4 * 128 / 256, 256>>>(conv_w + i * DI * KC,
                                        conv_b + i * DI);
    hmma_nk64<<<NR / 128, 256, SMEM_D>>>(
        p_xsh, p_xsl, p_xpwh + (size_t)i * 64 * DI, p_zb, p_dbc, DI);
    k_scan<<<B * 8, 256>>>(A_log + i * DI * DS, Dp + i * DI,
                           dt_w + i * DI * DTR, dt_b + i * DI);
    hmma_gemm<true><<<dim3(2, NR / 128), 256, SMEM_H>>>(
        p_yh, p_wo + (size_t)i * D * DI, out_b + i * D, p_h, D, DI);
  }

  k_ln_t<2><<<NR / 8, 256>>>(p_h, on_g, on_b, p_xnh, p_xnl);
  hmma_nk64<<<NR / 128, 256, SMEM_D>>>(p_xnh, p_xnl, p_opwh, op_b, out, D);
}